// round 14
// baseline (speedup 1.0000x reference)
#include <cuda_runtime.h>
#include <cuda_fp16.h>
#include <math.h>

// ---------------------------------------------------------------------------
// Problem constants (fixed shapes per reference)
// ---------------------------------------------------------------------------
#define MAXN 50048
#define MAXE 850048
#define D    128         // D_IN == D_OUT
#define DFF  512
#define NHEAD 8
#define HDIM 16
#define ALPHA 0.15f
#define SLOPE 0.2f
#define LNEPS 1e-5f

// ---------------------------------------------------------------------------
// Scratch (static device globals; no runtime allocation)
// ---------------------------------------------------------------------------
__device__ __half d_h16  [MAXN * D];    // LN1 output, fp16 (proj GEMM A input)
__device__ __half d_fh16 [MAXN * D];    // head proj, fp16 (gathered in attn)
__device__ __half d_ft16 [MAXN * D];    // tail proj, fp16 (node-local in attn)
__device__ __half d_fe16 [MAXN * D];    // ent proj, fp16 (gathered + alpha term)
__device__ __half d_g0   [MAXN * D];    // hop ping-pong (fp16)
__device__ __half d_g1   [MAXN * D];
__device__ float  d_rst  [MAXN * D];
__device__ __half d_x216 [MAXN * D];    // LN2 output, fp16 (FFN1 input)
__device__ __half d_y116 [MAXN * DFF];  // FFN intermediate, fp16
__device__ __half d_att16[MAXE * NHEAD];   // fp16 exp weights (hops 2-5)
__device__ float  d_inv  [MAXN * NHEAD];
__device__ int    d_csr  [MAXE];
__device__ int    d_deg  [MAXN];
__device__ int    d_cur  [MAXN];
__device__ int    d_row  [MAXN + 1];
__device__ int    d_part [64];
__device__ float  d_log  [MAXN];

// ---------------------------------------------------------------------------
// LayerNorm: one warp per row of 128 floats, fp16 output
// ---------------------------------------------------------------------------
__global__ void ln_kernel(const float* __restrict__ x,
                          const float* __restrict__ g,
                          const float* __restrict__ b,
                          __half* __restrict__ y, int n)
{
    int warp = (blockIdx.x * blockDim.x + threadIdx.x) >> 5;
    int lane = threadIdx.x & 31;
    if (warp >= n) return;
    const float4 v = *(const float4*)(x + (size_t)warp * D + lane * 4);
    float s  = v.x + v.y + v.z + v.w;
    float ss = v.x*v.x + v.y*v.y + v.z*v.z + v.w*v.w;
    #pragma unroll
    for (int off = 16; off; off >>= 1) {
        s  += __shfl_xor_sync(0xffffffffu, s,  off);
        ss += __shfl_xor_sync(0xffffffffu, ss, off);
    }
    float mean = s * (1.f / D);
    float var  = ss * (1.f / D) - mean * mean;
    float rstd = rsqrtf(var + LNEPS);
    const float4 gv = *(const float4*)(g + lane * 4);
    const float4 bv = *(const float4*)(b + lane * 4);
    uint2 out;
    __half2* ph = (__half2*)&out;
    ph[0] = __floats2half2_rn((v.x - mean) * rstd * gv.x + bv.x,
                              (v.y - mean) * rstd * gv.y + bv.y);
    ph[1] = __floats2half2_rn((v.z - mean) * rstd * gv.z + bv.z,
                              (v.w - mean) * rstd * gv.w + bv.w);
    *(uint2*)(y + (size_t)warp * D + lane * 4) = out;
}

// ---------------------------------------------------------------------------
// FP16 tensor-core GEMM machinery (mma.m16n8k16, fp32 accumulate)
// ---------------------------------------------------------------------------
#define PADH 12

__device__ __forceinline__ void mma_f16(float* c, const __half2* a, const __half2* b) {
    asm volatile(
        "mma.sync.aligned.m16n8k16.row.col.f32.f16.f16.f32 "
        "{%0,%1,%2,%3}, {%4,%5,%6,%7}, {%8,%9}, {%0,%1,%2,%3};\n"
        : "+f"(c[0]), "+f"(c[1]), "+f"(c[2]), "+f"(c[3])
        : "r"(*(const unsigned*)&a[0]), "r"(*(const unsigned*)&a[1]),
          "r"(*(const unsigned*)&a[2]), "r"(*(const unsigned*)&a[3]),
          "r"(*(const unsigned*)&b[0]), "r"(*(const unsigned*)&b[1]));
}

__device__ __forceinline__ float4 ld4(const float* p) {
    return *(const float4*)p;
}
__device__ __forceinline__ float4 ld4(const __half* p) {
    uint2 r = *(const uint2*)p;
    __half2 h0 = *(__half2*)&r.x;
    __half2 h1 = *(__half2*)&r.y;
    float2 a = __half22float2(h0);
    float2 b = __half22float2(h1);
    return make_float4(a.x, a.y, b.x, b.y);
}

template<typename AT, typename BT>
struct MmaCtx {
    const AT *Ap0, *Ap1;
    const BT *Bp0, *Bp1;
    bool av0, av1;
    int grow, gc2, wm, wn, g, t;
};

template<typename AT, typename BT>
__device__ __forceinline__ MmaCtx<AT, BT> make_ctx(const AT* A, const BT* B,
                                                   int m0, int n0, int M, int K,
                                                   int tid)
{
    MmaCtx<AT, BT> cx;
    int lane = tid & 31, wid = tid >> 5;
    cx.grow = tid >> 2;
    int gcol = (tid & 3) * 4;
    cx.gc2  = (tid & 3) * 2;
    cx.av0 = (m0 + cx.grow)      < M;
    cx.av1 = (m0 + cx.grow + 64) < M;
    cx.Ap0 = A + (size_t)(m0 + cx.grow)      * K + gcol;
    cx.Ap1 = A + (size_t)(m0 + cx.grow + 64) * K + gcol;
    cx.Bp0 = B + (size_t)(n0 + cx.grow)      * K + gcol;
    cx.Bp1 = B + (size_t)(n0 + cx.grow + 64) * K + gcol;
    cx.wm = (wid & 3) * 32;
    cx.wn = (wid >> 2) * 64;
    cx.g = lane >> 2;
    cx.t = lane & 3;
    return cx;
}

__device__ __forceinline__ void st_tile(__half2* s, int row, int c2, float4 v) {
    s[row * PADH + c2]     = __floats2half2_rn(v.x, v.y);
    s[row * PADH + c2 + 1] = __floats2half2_rn(v.z, v.w);
}

template<typename AT, typename BT, typename AccT>
__device__ __forceinline__ void mma_mainloop(
    const MmaCtx<AT, BT>& cx, int K, __half2 (*As)[128 * PADH], __half2 (*Bs)[128 * PADH],
    AccT& acc)
{
    {
        float4 a0 = cx.av0 ? ld4(cx.Ap0) : make_float4(0,0,0,0);
        float4 a1 = cx.av1 ? ld4(cx.Ap1) : make_float4(0,0,0,0);
        float4 b0 = ld4(cx.Bp0);
        float4 b1 = ld4(cx.Bp1);
        st_tile(As[0], cx.grow,      cx.gc2, a0);
        st_tile(As[0], cx.grow + 64, cx.gc2, a1);
        st_tile(Bs[0], cx.grow,      cx.gc2, b0);
        st_tile(Bs[0], cx.grow + 64, cx.gc2, b1);
    }
    __syncthreads();

    int nk = K >> 4;
    for (int it = 0; it < nk; ++it) {
        int buf = it & 1;
        bool more = (it + 1) < nk;
        float4 na0, na1, nb0, nb1;
        if (more) {
            int ko = (it + 1) * 16;
            na0 = cx.av0 ? ld4(cx.Ap0 + ko) : make_float4(0,0,0,0);
            na1 = cx.av1 ? ld4(cx.Ap1 + ko) : make_float4(0,0,0,0);
            nb0 = ld4(cx.Bp0 + ko);
            nb1 = ld4(cx.Bp1 + ko);
        }
        const __half2* as = As[buf];
        const __half2* bs = Bs[buf];
        {
            __half2 afr[2][4];
            #pragma unroll
            for (int i = 0; i < 2; i++) {
                int r0 = (cx.wm + i * 16 + cx.g) * PADH;
                int r8 = (cx.wm + i * 16 + 8 + cx.g) * PADH;
                afr[i][0] = as[r0 + cx.t];
                afr[i][1] = as[r8 + cx.t];
                afr[i][2] = as[r0 + cx.t + 4];
                afr[i][3] = as[r8 + cx.t + 4];
            }
            #pragma unroll
            for (int j = 0; j < 8; j++) {
                int nb = (cx.wn + j * 8 + cx.g) * PADH + cx.t;
                __half2 bfr[2];
                bfr[0] = bs[nb];
                bfr[1] = bs[nb + 4];
                mma_f16(acc[0][j], afr[0], bfr);
                mma_f16(acc[1][j], afr[1], bfr);
            }
        }
        if (more) {
            int nbuf = buf ^ 1;
            st_tile(As[nbuf], cx.grow,      cx.gc2, na0);
            st_tile(As[nbuf], cx.grow + 64, cx.gc2, na1);
            st_tile(Bs[nbuf], cx.grow,      cx.gc2, nb0);
            st_tile(Bs[nbuf], cx.grow + 64, cx.gc2, nb1);
        }
        __syncthreads();
    }
}

// ---------------------------------------------------------------------------
// Generic GEMM: C[M,Nc] = A @ B^T (+bias, +relu, +add)
// ---------------------------------------------------------------------------
template<bool RELU, bool HAS_BIAS, bool HAS_ADD, bool OUT_HALF, typename AT>
__global__ void __launch_bounds__(256)
mma_gemm_kernel(const AT* __restrict__ A,
                const float* __restrict__ B,
                const float* __restrict__ bias,
                const float* __restrict__ add,
                void* __restrict__ Cv,
                int M, int Nc, int K)
{
    __shared__ __half2 As[2][128 * PADH];
    __shared__ __half2 Bs[2][128 * PADH];
    int tid = threadIdx.x;
    int m0 = blockIdx.y * 128;
    int n0 = blockIdx.x * 128;
    MmaCtx<AT, float> cx = make_ctx(A, B, m0, n0, M, K, tid);

    float acc[2][8][4];
    #pragma unroll
    for (int i = 0; i < 2; i++)
        #pragma unroll
        for (int j = 0; j < 8; j++)
            #pragma unroll
            for (int q = 0; q < 4; q++) acc[i][j][q] = 0.f;

    mma_mainloop(cx, K, As, Bs, acc);

    #pragma unroll
    for (int j = 0; j < 8; j++) {
        int col = n0 + cx.wn + j * 8 + cx.t * 2;
        float bx = 0.f, by = 0.f;
        if (HAS_BIAS) { bx = bias[col]; by = bias[col + 1]; }
        #pragma unroll
        for (int i = 0; i < 2; i++) {
            int r0 = m0 + cx.wm + i * 16 + cx.g;
            int r1 = r0 + 8;
            float2 o0, o1;
            o0.x = acc[i][j][0] + bx; o0.y = acc[i][j][1] + by;
            o1.x = acc[i][j][2] + bx; o1.y = acc[i][j][3] + by;
            if (RELU) {
                o0.x = fmaxf(o0.x, 0.f); o0.y = fmaxf(o0.y, 0.f);
                o1.x = fmaxf(o1.x, 0.f); o1.y = fmaxf(o1.y, 0.f);
            }
            if (r0 < M) {
                if (HAS_ADD) {
                    float2 ad = *(const float2*)(add + (size_t)r0 * Nc + col);
                    o0.x += ad.x; o0.y += ad.y;
                }
                if (OUT_HALF)
                    *(__half2*)((__half*)Cv + (size_t)r0 * Nc + col) = __floats2half2_rn(o0.x, o0.y);
                else
                    *(float2*)((float*)Cv + (size_t)r0 * Nc + col) = o0;
            }
            if (r1 < M) {
                if (HAS_ADD) {
                    float2 ad = *(const float2*)(add + (size_t)r1 * Nc + col);
                    o1.x += ad.x; o1.y += ad.y;
                }
                if (OUT_HALF)
                    *(__half2*)((__half*)Cv + (size_t)r1 * Nc + col) = __floats2half2_rn(o1.x, o1.y);
                else
                    *(float2*)((float*)Cv + (size_t)r1 * Nc + col) = o1;
            }
        }
    }
}

// ---------------------------------------------------------------------------
// Fused projection GEMM: blockIdx.z selects {W_head->fh16, W_tail->ft16, W_ent->fe16}
// ---------------------------------------------------------------------------
__global__ void __launch_bounds__(256)
proj_gemm_kernel(const __half* __restrict__ A,
                 const float* __restrict__ W_head,
                 const float* __restrict__ W_tail,
                 const float* __restrict__ W_ent,
                 int M)
{
    __shared__ __half2 As[2][128 * PADH];
    __shared__ __half2 Bs[2][128 * PADH];
    int tid = threadIdx.x;
    int z = blockIdx.z;
    int m0 = blockIdx.y * 128;
    const float* B = (z == 0) ? W_head : (z == 1) ? W_tail : W_ent;
    MmaCtx<__half, float> cx = make_ctx(A, B, m0, 0, M, D, tid);

    float acc[2][8][4];
    #pragma unroll
    for (int i = 0; i < 2; i++)
        #pragma unroll
        for (int j = 0; j < 8; j++)
            #pragma unroll
            for (int q = 0; q < 4; q++) acc[i][j][q] = 0.f;

    mma_mainloop(cx, D, As, Bs, acc);

    __half* C16 = (z == 0) ? d_fh16 : (z == 1) ? d_ft16 : d_fe16;
    #pragma unroll
    for (int j = 0; j < 8; j++) {
        int col = cx.wn + j * 8 + cx.t * 2;
        #pragma unroll
        for (int i = 0; i < 2; i++) {
            int r0 = m0 + cx.wm + i * 16 + cx.g;
            int r1 = r0 + 8;
            if (r0 < M) *(__half2*)(C16 + (size_t)r0 * D + col)
                = __floats2half2_rn(acc[i][j][0], acc[i][j][1]);
            if (r1 < M) *(__half2*)(C16 + (size_t)r1 * D + col)
                = __floats2half2_rn(acc[i][j][2], acc[i][j][3]);
        }
    }
}

// ---------------------------------------------------------------------------
// Graph preprocessing: degree count + hierarchical exclusive scan + CSR fill
// ---------------------------------------------------------------------------
__global__ void deg_kernel(const int* __restrict__ dst, int e)
{
    int i = blockIdx.x * blockDim.x + threadIdx.x;
    if (i < e) atomicAdd(&d_deg[dst[i]], 1);
}

__global__ void scanA_kernel(int n)
{
    __shared__ int wsum[32];
    int i = blockIdx.x * 1024 + threadIdx.x;
    int lane = threadIdx.x & 31, w = threadIdx.x >> 5;
    int v = (i < n) ? d_deg[i] : 0;
    #pragma unroll
    for (int off = 16; off; off >>= 1)
        v += __shfl_xor_sync(0xffffffffu, v, off);
    if (lane == 0) wsum[w] = v;
    __syncthreads();
    if (w == 0) {
        int s = wsum[lane];
        #pragma unroll
        for (int off = 16; off; off >>= 1)
            s += __shfl_xor_sync(0xffffffffu, s, off);
        if (lane == 0) d_part[blockIdx.x] = s;
    }
}

__global__ void scanB_kernel(int nb, int n)
{
    int run = 0;
    for (int i = 0; i < nb; i++) {
        int v = d_part[i];
        d_part[i] = run;
        run += v;
    }
    d_row[n] = run;
}

// scanC also computes log(deg)
__global__ void scanC_kernel(int n)
{
    __shared__ int wsum[32];
    int i = blockIdx.x * 1024 + threadIdx.x;
    int lane = threadIdx.x & 31, w = threadIdx.x >> 5;
    int v = (i < n) ? d_deg[i] : 0;
    int incl = v;
    #pragma unroll
    for (int off = 1; off < 32; off <<= 1) {
        int t = __shfl_up_sync(0xffffffffu, incl, off);
        if (lane >= off) incl += t;
    }
    if (lane == 31) wsum[w] = incl;
    __syncthreads();
    if (w == 0) {
        int ws = wsum[lane];
        int wi = ws;
        #pragma unroll
        for (int off = 1; off < 32; off <<= 1) {
            int t = __shfl_up_sync(0xffffffffu, wi, off);
            if (lane >= off) wi += t;
        }
        wsum[lane] = wi - ws;
    }
    __syncthreads();
    int excl = d_part[blockIdx.x] + wsum[w] + (incl - v);
    if (i < n) {
        d_row[i] = excl;
        d_cur[i] = excl;
        d_log[i] = logf((float)v);
    }
}

__global__ void fill_kernel(const int* __restrict__ src,
                            const int* __restrict__ dst, int e)
{
    int i = blockIdx.x * blockDim.x + threadIdx.x;
    if (i >= e) return;
    int p = atomicAdd(&d_cur[dst[i]], 1);
    d_csr[p] = src[i];
}

// ---------------------------------------------------------------------------
// 16-lane row gather: lane sub (0..15) owns dims [8*sub, 8*sub+8), LDG.128
// ---------------------------------------------------------------------------
__device__ __forceinline__ void gather_h8(const __half* __restrict__ base,
                                          int node, int sub, float* f)
{
    uint4 r = *(const uint4*)(base + (size_t)node * D + sub * 8);
    const __half2* h = (const __half2*)&r;
    #pragma unroll
    for (int i = 0; i < 4; i++) {
        float2 t = __half22float2(h[i]);
        f[2*i]   = t.x;
        f[2*i+1] = t.y;
    }
}

// ---------------------------------------------------------------------------
// FUSED attention + edge softmax + hop 1: one warp per destination node.
// Single pass over edges: gathers fh (logit) and fe (aggregation), computes
// x = exp(logit) in registers (no max-shift needed; logits provably small),
// accumulates unnormalized hop-1 sum, writes att16 + d_inv for hops 2-5,
// and writes hop-1 output g0 = inv*acc + alpha*fe[node].
// ---------------------------------------------------------------------------
__global__ void attn_hop1_kernel(const float* __restrict__ attnw,
                                 __half* __restrict__ fout, int n)
{
    int warp = (blockIdx.x * blockDim.x + threadIdx.x) >> 5;
    int lane = threadIdx.x & 31;
    if (warp >= n) return;
    int node = warp;
    int half = lane >> 4;
    int sub  = lane & 15;
    int h    = sub >> 1;

    float ftv[8], aw[8];
    gather_h8(d_ft16, node, sub, ftv);
    {
        float4 a0 = *(const float4*)(attnw + sub * 8);
        float4 a1 = *(const float4*)(attnw + sub * 8 + 4);
        aw[0]=a0.x; aw[1]=a0.y; aw[2]=a0.z; aw[3]=a0.w;
        aw[4]=a1.x; aw[5]=a1.y; aw[6]=a1.z; aw[7]=a1.w;
    }
    float li = d_log[node] * (1.f / HDIM);
    int begin = d_row[node], end = d_row[node + 1];

    float acc[8];
    #pragma unroll
    for (int j = 0; j < 8; j++) acc[j] = 0.f;
    float ssum = 0.f;   // per-half head sum (identical on pair lanes)

    int s2 = begin;
    for (; s2 + 3 < end; s2 += 4) {
        int e0 = s2 + half;
        int e1 = s2 + 2 + half;
        int sn0 = d_csr[e0], sn1 = d_csr[e1];
        float fh0[8], fh1[8], fe0[8], fe1[8];
        gather_h8(d_fh16, sn0, sub, fh0);
        gather_h8(d_fh16, sn1, sub, fh1);
        gather_h8(d_fe16, sn0, sub, fe0);
        gather_h8(d_fe16, sn1, sub, fe1);
        float p0 = 0.f, p1 = 0.f;
        #pragma unroll
        for (int j = 0; j < 8; j++) {
            float q0 = fh0[j] * ftv[j]; q0 = q0 > 0.f ? q0 : SLOPE * q0;
            float q1 = fh1[j] * ftv[j]; q1 = q1 > 0.f ? q1 : SLOPE * q1;
            p0 += q0 * aw[j];
            p1 += q1 * aw[j];
        }
        p0 += __shfl_xor_sync(0xffffffffu, p0, 1);
        p1 += __shfl_xor_sync(0xffffffffu, p1, 1);
        float x0 = expf(p0 * li);
        float x1 = expf(p1 * li);
        #pragma unroll
        for (int j = 0; j < 8; j++)
            acc[j] += x0 * fe0[j] + x1 * fe1[j];
        ssum += x0 + x1;
        if ((sub & 1) == 0) {
            d_att16[(size_t)e0 * NHEAD + h] = __float2half_rn(x0);
            d_att16[(size_t)e1 * NHEAD + h] = __float2half_rn(x1);
        }
    }
    for (; s2 < end; s2 += 2) {
        int e = s2 + half;
        bool vld = e < end;
        int sn = vld ? d_csr[e] : node;
        float fh[8], fe[8];
        gather_h8(d_fh16, sn, sub, fh);
        gather_h8(d_fe16, sn, sub, fe);
        float p = 0.f;
        #pragma unroll
        for (int j = 0; j < 8; j++) {
            float q = fh[j] * ftv[j]; q = q > 0.f ? q : SLOPE * q;
            p += q * aw[j];
        }
        p += __shfl_xor_sync(0xffffffffu, p, 1);
        float x = vld ? expf(p * li) : 0.f;
        #pragma unroll
        for (int j = 0; j < 8; j++)
            acc[j] += x * fe[j];
        ssum += x;
        if (vld && (sub & 1) == 0)
            d_att16[(size_t)e * NHEAD + h] = __float2half_rn(x);
    }

    // cross-half reduction: pair lanes already hold identical per-half values
    ssum += __shfl_xor_sync(0xffffffffu, ssum, 16);
    #pragma unroll
    for (int j = 0; j < 8; j++)
        acc[j] += __shfl_xor_sync(0xffffffffu, acc[j], 16);

    float inv = (1.f - ALPHA) / ssum;
    if ((sub & 1) == 0 && half == 0)
        d_inv[(size_t)node * NHEAD + h] = inv;

    if (half == 0) {
        float fe[8];
        gather_h8(d_fe16, node, sub, fe);
        uint4 out;
        __half2* ph = (__half2*)&out;
        ph[0] = __floats2half2_rn(inv*acc[0] + ALPHA*fe[0], inv*acc[1] + ALPHA*fe[1]);
        ph[1] = __floats2half2_rn(inv*acc[2] + ALPHA*fe[2], inv*acc[3] + ALPHA*fe[3]);
        ph[2] = __floats2half2_rn(inv*acc[4] + ALPHA*fe[4], inv*acc[5] + ALPHA*fe[5]);
        ph[3] = __floats2half2_rn(inv*acc[6] + ALPHA*fe[6], inv*acc[7] + ALPHA*fe[7]);
        *(uint4*)(fout + (size_t)node * D + sub * 8) = out;
    }
}

// ---------------------------------------------------------------------------
// Hop aggregation: half-warp per edge, 8 edges per warp-iter (4 per half),
// direct csr loads, LDG.128 gathers.
// ---------------------------------------------------------------------------
__device__ __forceinline__ void hop_agg(const __half* __restrict__ fin,
                                        int node, int half, int sub, int h,
                                        float* o)
{
    int begin = d_row[node], end = d_row[node + 1];
    float acc[8];
    #pragma unroll
    for (int j = 0; j < 8; j++) acc[j] = 0.f;

    int s2 = begin;
    for (; s2 + 7 < end; s2 += 8) {
        int e0 = s2 + half;
        int e1 = s2 + 2 + half;
        int e2 = s2 + 4 + half;
        int e3 = s2 + 6 + half;
        int sn0 = d_csr[e0], sn1 = d_csr[e1];
        int sn2 = d_csr[e2], sn3 = d_csr[e3];
        float a0 = __half2float(d_att16[(size_t)e0 * NHEAD + h]);
        float a1 = __half2float(d_att16[(size_t)e1 * NHEAD + h]);
        float a2 = __half2float(d_att16[(size_t)e2 * NHEAD + h]);
        float a3 = __half2float(d_att16[(size_t)e3 * NHEAD + h]);
        float f0[8], f1[8], f2[8], f3[8];
        gather_h8(fin, sn0, sub, f0);
        gather_h8(fin, sn1, sub, f1);
        gather_h8(fin, sn2, sub, f2);
        gather_h8(fin, sn3, sub, f3);
        #pragma unroll
        for (int j = 0; j < 8; j++)
            acc[j] += (a0 * f0[j] + a1 * f1[j]) + (a2 * f2[j] + a3 * f3[j]);
    }
    for (; s2 + 3 < end; s2 += 4) {
        int e0 = s2 + half;
        int e1 = s2 + 2 + half;
        int sn0 = d_csr[e0], sn1 = d_csr[e1];
        float a0 = __half2float(d_att16[(size_t)e0 * NHEAD + h]);
        float a1 = __half2float(d_att16[(size_t)e1 * NHEAD + h]);
        float f0[8], f1[8];
        gather_h8(fin, sn0, sub, f0);
        gather_h8(fin, sn1, sub, f1);
        #pragma unroll
        for (int j = 0; j < 8; j++)
            acc[j] += a0 * f0[j] + a1 * f1[j];
    }
    for (; s2 < end; s2 += 2) {
        int e = s2 + half;
        bool vld = e < end;
        int sn = vld ? d_csr[e] : node;
        float a = vld ? __half2float(d_att16[(size_t)e * NHEAD + h]) : 0.f;
        float f[8];
        gather_h8(fin, sn, sub, f);
        #pragma unroll
        for (int j = 0; j < 8; j++)
            acc[j] += a * f[j];
    }
    #pragma unroll
    for (int j = 0; j < 8; j++)
        acc[j] += __shfl_xor_sync(0xffffffffu, acc[j], 16);

    float inv = d_inv[(size_t)node * NHEAD + h];   // includes (1-alpha)
    float fe[8];
    gather_h8(d_fe16, node, sub, fe);
    #pragma unroll
    for (int j = 0; j < 8; j++)
        o[j] = inv * acc[j] + ALPHA * fe[j];
}

// intermediate hop: write fp16 (half 0 lanes store uint4)
__global__ void hop_kernel(const __half* __restrict__ fin,
                           __half* __restrict__ fout, int n)
{
    int warp = (blockIdx.x * blockDim.x + threadIdx.x) >> 5;
    int lane = threadIdx.x & 31;
    if (warp >= n) return;
    int half = lane >> 4, sub = lane & 15, h = sub >> 1;
    float o[8];
    hop_agg(fin, warp, half, sub, h, o);
    if (half == 0) {
        uint4 out;
        __half2* ph = (__half2*)&out;
        ph[0] = __floats2half2_rn(o[0], o[1]);
        ph[1] = __floats2half2_rn(o[2], o[3]);
        ph[2] = __floats2half2_rn(o[4], o[5]);
        ph[3] = __floats2half2_rn(o[6], o[7]);
        *(uint4*)(fout + (size_t)warp * D + sub * 8) = out;
    }
}

// last hop fused with residual + LN2: rst = o + feat (fp32); x2 = LN(rst) (fp16)
__global__ void hop_last_kernel(const __half* __restrict__ fin,
                                const float* __restrict__ feat,
                                const float* __restrict__ g,
                                const float* __restrict__ b, int n)
{
    int warp = (blockIdx.x * blockDim.x + threadIdx.x) >> 5;
    int lane = threadIdx.x & 31;
    if (warp >= n) return;
    int half = lane >> 4, sub = lane & 15, h = sub >> 1;
    float o[8];
    hop_agg(fin, warp, half, sub, h, o);

    float r[8];
    {
        float4 t0 = *(const float4*)(feat + (size_t)warp * D + sub * 8);
        float4 t1 = *(const float4*)(feat + (size_t)warp * D + sub * 8 + 4);
        r[0]=o[0]+t0.x; r[1]=o[1]+t0.y; r[2]=o[2]+t0.z; r[3]=o[3]+t0.w;
        r[4]=o[4]+t1.x; r[5]=o[5]+t1.y; r[6]=o[6]+t1.z; r[7]=o[7]+t1.w;
    }
    if (half == 0) {
        *(float4*)(d_rst + (size_t)warp * D + sub * 8)     = make_float4(r[0],r[1],r[2],r[3]);
        *(float4*)(d_rst + (size_t)warp * D + sub * 8 + 4) = make_float4(r[4],r[5],r[6],r[7]);
    }
    float s = 0.f, ss = 0.f;
    #pragma unroll
    for (int j = 0; j < 8; j++) { s += r[j]; ss += r[j] * r[j]; }
    #pragma unroll
    for (int off = 8; off; off >>= 1) {
        s  += __shfl_xor_sync(0xffffffffu, s,  off);
        ss += __shfl_xor_sync(0xffffffffu, ss, off);
    }
    float mean = s * (1.f / D);
    float var  = ss * (1.f / D) - mean * mean;
    float rstd = rsqrtf(var + LNEPS);
    if (half == 0) {
        float4 g0 = *(const float4*)(g + sub * 8);
        float4 g1 = *(const float4*)(g + sub * 8 + 4);
        float4 b0 = *(const float4*)(b + sub * 8);
        float4 b1 = *(const float4*)(b + sub * 8 + 4);
        uint4 out;
        __half2* ph = (__half2*)&out;
        ph[0] = __floats2half2_rn((r[0]-mean)*rstd*g0.x + b0.x,
                                  (r[1]-mean)*rstd*g0.y + b0.y);
        ph[1] = __floats2half2_rn((r[2]-mean)*rstd*g0.z + b0.z,
                                  (r[3]-mean)*rstd*g0.w + b0.w);
        ph[2] = __floats2half2_rn((r[4]-mean)*rstd*g1.x + b1.x,
                                  (r[5]-mean)*rstd*g1.y + b1.y);
        ph[3] = __floats2half2_rn((r[6]-mean)*rstd*g1.z + b1.z,
                                  (r[7]-mean)*rstd*g1.w + b1.w);
        *(uint4*)(d_x216 + (size_t)warp * D + sub * 8) = out;
    }
}

// ---------------------------------------------------------------------------
// Host launch: CSR build chain forked onto a side stream, overlapped with
// LN1 + projections; joined before the fused attn+hop1.
// ---------------------------------------------------------------------------
extern "C" void kernel_launch(void* const* d_in, const int* in_sizes, int n_in,
                              void* d_out, int out_size)
{
    const float* feat  = (const float*)d_in[0];
    const int*   src   = (const int*)  d_in[1];
    const int*   dst   = (const int*)  d_in[2];
    const float* ln1_g = (const float*)d_in[3];
    const float* ln1_b = (const float*)d_in[4];
    const float* W_head= (const float*)d_in[5];
    const float* W_tail= (const float*)d_in[6];
    const float* W_ent = (const float*)d_in[7];
    const float* attnw = (const float*)d_in[8];
    const float* ln2_g = (const float*)d_in[9];
    const float* ln2_b = (const float*)d_in[10];
    const float* W_ff1 = (const float*)d_in[11];
    const float* b_ff1 = (const float*)d_in[12];
    const float* W_ff2 = (const float*)d_in[13];
    const float* b_ff2 = (const float*)d_in[14];

    int n = in_sizes[0] / D;
    int e = in_sizes[1];

    float *p_rst;
    __half *p_h16, *p_g0, *p_g1, *p_fe16, *p_x216, *p_y116;
    int *p_deg;
    cudaGetSymbolAddress((void**)&p_h16,  d_h16);
    cudaGetSymbolAddress((void**)&p_g0,   d_g0);
    cudaGetSymbolAddress((void**)&p_g1,   d_g1);
    cudaGetSymbolAddress((void**)&p_rst,  d_rst);
    cudaGetSymbolAddress((void**)&p_x216, d_x216);
    cudaGetSymbolAddress((void**)&p_y116, d_y116);
    cudaGetSymbolAddress((void**)&p_deg,  d_deg);
    cudaGetSymbolAddress((void**)&p_fe16, d_fe16);

    // One-time stream/event creation (host resources, not device memory).
    static cudaStream_t s_side = nullptr;
    static cudaEvent_t  ev_fork = nullptr, ev_join = nullptr;
    if (s_side == nullptr) {
        cudaStreamCreateWithFlags(&s_side, cudaStreamNonBlocking);
        cudaEventCreateWithFlags(&ev_fork, cudaEventDisableTiming);
        cudaEventCreateWithFlags(&ev_join, cudaEventDisableTiming);
    }

    const int TPB = 256;
    int rowBlocks  = (n * 32 + TPB - 1) / TPB;
    int edgeBlocks = (e + TPB - 1) / TPB;
    int nb = (n + 1023) / 1024;

    // Fork side stream off the main (capture) stream.
    cudaEventRecord(ev_fork, 0);
    cudaStreamWaitEvent(s_side, ev_fork, 0);

    // Side stream: CSR build chain (independent of LN1/projections).
    cudaMemsetAsync(p_deg, 0, (size_t)n * sizeof(int), s_side);
    deg_kernel<<<edgeBlocks, TPB, 0, s_side>>>(dst, e);
    scanA_kernel<<<nb, 1024, 0, s_side>>>(n);
    scanB_kernel<<<1, 1, 0, s_side>>>(nb, n);
    scanC_kernel<<<nb, 1024, 0, s_side>>>(n);
    fill_kernel<<<edgeBlocks, TPB, 0, s_side>>>(src, dst, e);
    cudaEventRecord(ev_join, s_side);

    // Main stream: LN1 (fp16 out) + projections (fp16 A, concurrent with CSR).
    ln_kernel<<<rowBlocks, TPB>>>(feat, ln1_g, ln1_b, p_h16, n);
    dim3 gproj(1, (n + 127) / 128, 3);
    proj_gemm_kernel<<<gproj, 256>>>(p_h16, W_head, W_tail, W_ent, n);

    // Join: fused attn+hop1 needs both CSR and projections.
    cudaStreamWaitEvent(0, ev_join, 0);

    // 4. fused attention softmax + hop 1 -> g0
    attn_hop1_kernel<<<rowBlocks, TPB>>>(attnw, p_g0, n);

    // 5. hops 2-5 (fp16 ping-pong), last hop fused with residual+LN2
    hop_kernel<<<rowBlocks, TPB>>>(p_g0, p_g1, n);
    hop_kernel<<<rowBlocks, TPB>>>(p_g1, p_g0, n);
    hop_kernel<<<rowBlocks, TPB>>>(p_g0, p_g1, n);
    hop_last_kernel<<<rowBlocks, TPB>>>(p_g1, feat, ln2_g, ln2_b, n);

    // 6. FFN (fp16 tensor cores, fp16 intermediate + fp16 x2 input)
    dim3 gff1(DFF / 128, (n + 127) / 128);
    mma_gemm_kernel<true, true, false, true, __half><<<gff1, 256>>>(
        p_x216, W_ff1, b_ff1, nullptr, p_y116, n, DFF, D);
    dim3 gff2(D / 128, (n + 127) / 128);
    mma_gemm_kernel<false, true, true, false, __half><<<gff2, 256>>>(
        p_y116, W_ff2, b_ff2, p_rst, d_out, n, D, DFF);
}

// round 15
// speedup vs baseline: 1.0063x; 1.0063x over previous
#include <cuda_runtime.h>
#include <cuda_fp16.h>
#include <math.h>

// ---------------------------------------------------------------------------
// Problem constants (fixed shapes per reference)
// ---------------------------------------------------------------------------
#define MAXN 50048
#define MAXE 850048
#define D    128         // D_IN == D_OUT
#define DFF  512
#define NHEAD 8
#define HDIM 16
#define ALPHA 0.15f
#define SLOPE 0.2f
#define LNEPS 1e-5f

// ---------------------------------------------------------------------------
// Scratch (static device globals; no runtime allocation)
// ---------------------------------------------------------------------------
__device__ __half d_h16  [MAXN * D];    // LN1 output, fp16 (proj GEMM A input)
__device__ __half d_fh16 [MAXN * D];    // head proj, fp16 (gathered in attn)
__device__ __half d_ft16 [MAXN * D];    // tail proj, fp16 (node-local in attn)
__device__ __half d_fe16 [MAXN * D];    // ent proj, fp16 (gathered + alpha term)
__device__ __half d_g0   [MAXN * D];    // hop ping-pong (fp16)
__device__ __half d_g1   [MAXN * D];
__device__ __half d_rst16[MAXN * D];    // residual, fp16 (FFN2 add input)
__device__ __half d_x216 [MAXN * D];    // LN2 output, fp16 (FFN1 input)
__device__ __half d_y116 [MAXN * DFF];  // FFN intermediate, fp16
__device__ __half d_att16[MAXE * NHEAD];   // fp16 exp weights (hop loop)
__device__ float  d_inv  [MAXN * NHEAD];
__device__ int    d_csr  [MAXE];
__device__ int    d_deg  [MAXN];
__device__ int    d_cur  [MAXN];
__device__ int    d_row  [MAXN + 1];
__device__ int    d_part [64];
__device__ float  d_log  [MAXN];

// ---------------------------------------------------------------------------
// LayerNorm: one warp per row of 128 floats, fp16 output
// ---------------------------------------------------------------------------
__global__ void ln_kernel(const float* __restrict__ x,
                          const float* __restrict__ g,
                          const float* __restrict__ b,
                          __half* __restrict__ y, int n)
{
    int warp = (blockIdx.x * blockDim.x + threadIdx.x) >> 5;
    int lane = threadIdx.x & 31;
    if (warp >= n) return;
    const float4 v = *(const float4*)(x + (size_t)warp * D + lane * 4);
    float s  = v.x + v.y + v.z + v.w;
    float ss = v.x*v.x + v.y*v.y + v.z*v.z + v.w*v.w;
    #pragma unroll
    for (int off = 16; off; off >>= 1) {
        s  += __shfl_xor_sync(0xffffffffu, s,  off);
        ss += __shfl_xor_sync(0xffffffffu, ss, off);
    }
    float mean = s * (1.f / D);
    float var  = ss * (1.f / D) - mean * mean;
    float rstd = rsqrtf(var + LNEPS);
    const float4 gv = *(const float4*)(g + lane * 4);
    const float4 bv = *(const float4*)(b + lane * 4);
    uint2 out;
    __half2* ph = (__half2*)&out;
    ph[0] = __floats2half2_rn((v.x - mean) * rstd * gv.x + bv.x,
                              (v.y - mean) * rstd * gv.y + bv.y);
    ph[1] = __floats2half2_rn((v.z - mean) * rstd * gv.z + bv.z,
                              (v.w - mean) * rstd * gv.w + bv.w);
    *(uint2*)(y + (size_t)warp * D + lane * 4) = out;
}

// ---------------------------------------------------------------------------
// FP16 tensor-core GEMM machinery (mma.m16n8k16, fp32 accumulate)
// ---------------------------------------------------------------------------
#define PADH 12

__device__ __forceinline__ void mma_f16(float* c, const __half2* a, const __half2* b) {
    asm volatile(
        "mma.sync.aligned.m16n8k16.row.col.f32.f16.f16.f32 "
        "{%0,%1,%2,%3}, {%4,%5,%6,%7}, {%8,%9}, {%0,%1,%2,%3};\n"
        : "+f"(c[0]), "+f"(c[1]), "+f"(c[2]), "+f"(c[3])
        : "r"(*(const unsigned*)&a[0]), "r"(*(const unsigned*)&a[1]),
          "r"(*(const unsigned*)&a[2]), "r"(*(const unsigned*)&a[3]),
          "r"(*(const unsigned*)&b[0]), "r"(*(const unsigned*)&b[1]));
}

__device__ __forceinline__ float4 ld4(const float* p) {
    return *(const float4*)p;
}
__device__ __forceinline__ float4 ld4(const __half* p) {
    uint2 r = *(const uint2*)p;
    __half2 h0 = *(__half2*)&r.x;
    __half2 h1 = *(__half2*)&r.y;
    float2 a = __half22float2(h0);
    float2 b = __half22float2(h1);
    return make_float4(a.x, a.y, b.x, b.y);
}

template<typename AT, typename BT>
struct MmaCtx {
    const AT *Ap0, *Ap1;
    const BT *Bp0, *Bp1;
    bool av0, av1;
    int grow, gc2, wm, wn, g, t;
};

template<typename AT, typename BT>
__device__ __forceinline__ MmaCtx<AT, BT> make_ctx(const AT* A, const BT* B,
                                                   int m0, int n0, int M, int K,
                                                   int tid)
{
    MmaCtx<AT, BT> cx;
    int lane = tid & 31, wid = tid >> 5;
    cx.grow = tid >> 2;
    int gcol = (tid & 3) * 4;
    cx.gc2  = (tid & 3) * 2;
    cx.av0 = (m0 + cx.grow)      < M;
    cx.av1 = (m0 + cx.grow + 64) < M;
    cx.Ap0 = A + (size_t)(m0 + cx.grow)      * K + gcol;
    cx.Ap1 = A + (size_t)(m0 + cx.grow + 64) * K + gcol;
    cx.Bp0 = B + (size_t)(n0 + cx.grow)      * K + gcol;
    cx.Bp1 = B + (size_t)(n0 + cx.grow + 64) * K + gcol;
    cx.wm = (wid & 3) * 32;
    cx.wn = (wid >> 2) * 64;
    cx.g = lane >> 2;
    cx.t = lane & 3;
    return cx;
}

__device__ __forceinline__ void st_tile(__half2* s, int row, int c2, float4 v) {
    s[row * PADH + c2]     = __floats2half2_rn(v.x, v.y);
    s[row * PADH + c2 + 1] = __floats2half2_rn(v.z, v.w);
}

template<typename AT, typename BT, typename AccT>
__device__ __forceinline__ void mma_mainloop(
    const MmaCtx<AT, BT>& cx, int K, __half2 (*As)[128 * PADH], __half2 (*Bs)[128 * PADH],
    AccT& acc)
{
    {
        float4 a0 = cx.av0 ? ld4(cx.Ap0) : make_float4(0,0,0,0);
        float4 a1 = cx.av1 ? ld4(cx.Ap1) : make_float4(0,0,0,0);
        float4 b0 = ld4(cx.Bp0);
        float4 b1 = ld4(cx.Bp1);
        st_tile(As[0], cx.grow,      cx.gc2, a0);
        st_tile(As[0], cx.grow + 64, cx.gc2, a1);
        st_tile(Bs[0], cx.grow,      cx.gc2, b0);
        st_tile(Bs[0], cx.grow + 64, cx.gc2, b1);
    }
    __syncthreads();

    int nk = K >> 4;
    for (int it = 0; it < nk; ++it) {
        int buf = it & 1;
        bool more = (it + 1) < nk;
        float4 na0, na1, nb0, nb1;
        if (more) {
            int ko = (it + 1) * 16;
            na0 = cx.av0 ? ld4(cx.Ap0 + ko) : make_float4(0,0,0,0);
            na1 = cx.av1 ? ld4(cx.Ap1 + ko) : make_float4(0,0,0,0);
            nb0 = ld4(cx.Bp0 + ko);
            nb1 = ld4(cx.Bp1 + ko);
        }
        const __half2* as = As[buf];
        const __half2* bs = Bs[buf];
        {
            __half2 afr[2][4];
            #pragma unroll
            for (int i = 0; i < 2; i++) {
                int r0 = (cx.wm + i * 16 + cx.g) * PADH;
                int r8 = (cx.wm + i * 16 + 8 + cx.g) * PADH;
                afr[i][0] = as[r0 + cx.t];
                afr[i][1] = as[r8 + cx.t];
                afr[i][2] = as[r0 + cx.t + 4];
                afr[i][3] = as[r8 + cx.t + 4];
            }
            #pragma unroll
            for (int j = 0; j < 8; j++) {
                int nb = (cx.wn + j * 8 + cx.g) * PADH + cx.t;
                __half2 bfr[2];
                bfr[0] = bs[nb];
                bfr[1] = bs[nb + 4];
                mma_f16(acc[0][j], afr[0], bfr);
                mma_f16(acc[1][j], afr[1], bfr);
            }
        }
        if (more) {
            int nbuf = buf ^ 1;
            st_tile(As[nbuf], cx.grow,      cx.gc2, na0);
            st_tile(As[nbuf], cx.grow + 64, cx.gc2, na1);
            st_tile(Bs[nbuf], cx.grow,      cx.gc2, nb0);
            st_tile(Bs[nbuf], cx.grow + 64, cx.gc2, nb1);
        }
        __syncthreads();
    }
}

// ---------------------------------------------------------------------------
// Generic GEMM: C[M,Nc] = A @ B^T (+bias, +relu, +add[fp16])
// ---------------------------------------------------------------------------
template<bool RELU, bool HAS_BIAS, bool HAS_ADD, bool OUT_HALF, typename AT>
__global__ void __launch_bounds__(256)
mma_gemm_kernel(const AT* __restrict__ A,
                const float* __restrict__ B,
                const float* __restrict__ bias,
                const __half* __restrict__ add,
                void* __restrict__ Cv,
                int M, int Nc, int K)
{
    __shared__ __half2 As[2][128 * PADH];
    __shared__ __half2 Bs[2][128 * PADH];
    int tid = threadIdx.x;
    int m0 = blockIdx.y * 128;
    int n0 = blockIdx.x * 128;
    MmaCtx<AT, float> cx = make_ctx(A, B, m0, n0, M, K, tid);

    float acc[2][8][4];
    #pragma unroll
    for (int i = 0; i < 2; i++)
        #pragma unroll
        for (int j = 0; j < 8; j++)
            #pragma unroll
            for (int q = 0; q < 4; q++) acc[i][j][q] = 0.f;

    mma_mainloop(cx, K, As, Bs, acc);

    #pragma unroll
    for (int j = 0; j < 8; j++) {
        int col = n0 + cx.wn + j * 8 + cx.t * 2;
        float bx = 0.f, by = 0.f;
        if (HAS_BIAS) { bx = bias[col]; by = bias[col + 1]; }
        #pragma unroll
        for (int i = 0; i < 2; i++) {
            int r0 = m0 + cx.wm + i * 16 + cx.g;
            int r1 = r0 + 8;
            float2 o0, o1;
            o0.x = acc[i][j][0] + bx; o0.y = acc[i][j][1] + by;
            o1.x = acc[i][j][2] + bx; o1.y = acc[i][j][3] + by;
            if (RELU) {
                o0.x = fmaxf(o0.x, 0.f); o0.y = fmaxf(o0.y, 0.f);
                o1.x = fmaxf(o1.x, 0.f); o1.y = fmaxf(o1.y, 0.f);
            }
            if (r0 < M) {
                if (HAS_ADD) {
                    float2 ad = __half22float2(*(const __half2*)(add + (size_t)r0 * Nc + col));
                    o0.x += ad.x; o0.y += ad.y;
                }
                if (OUT_HALF)
                    *(__half2*)((__half*)Cv + (size_t)r0 * Nc + col) = __floats2half2_rn(o0.x, o0.y);
                else
                    *(float2*)((float*)Cv + (size_t)r0 * Nc + col) = o0;
            }
            if (r1 < M) {
                if (HAS_ADD) {
                    float2 ad = __half22float2(*(const __half2*)(add + (size_t)r1 * Nc + col));
                    o1.x += ad.x; o1.y += ad.y;
                }
                if (OUT_HALF)
                    *(__half2*)((__half*)Cv + (size_t)r1 * Nc + col) = __floats2half2_rn(o1.x, o1.y);
                else
                    *(float2*)((float*)Cv + (size_t)r1 * Nc + col) = o1;
            }
        }
    }
}

// ---------------------------------------------------------------------------
// Fused projection GEMM: blockIdx.z selects {W_head->fh16, W_tail->ft16, W_ent->fe16}
// ---------------------------------------------------------------------------
__global__ void __launch_bounds__(256)
proj_gemm_kernel(const __half* __restrict__ A,
                 const float* __restrict__ W_head,
                 const float* __restrict__ W_tail,
                 const float* __restrict__ W_ent,
                 int M)
{
    __shared__ __half2 As[2][128 * PADH];
    __shared__ __half2 Bs[2][128 * PADH];
    int tid = threadIdx.x;
    int z = blockIdx.z;
    int m0 = blockIdx.y * 128;
    const float* B = (z == 0) ? W_head : (z == 1) ? W_tail : W_ent;
    MmaCtx<__half, float> cx = make_ctx(A, B, m0, 0, M, D, tid);

    float acc[2][8][4];
    #pragma unroll
    for (int i = 0; i < 2; i++)
        #pragma unroll
        for (int j = 0; j < 8; j++)
            #pragma unroll
            for (int q = 0; q < 4; q++) acc[i][j][q] = 0.f;

    mma_mainloop(cx, D, As, Bs, acc);

    __half* C16 = (z == 0) ? d_fh16 : (z == 1) ? d_ft16 : d_fe16;
    #pragma unroll
    for (int j = 0; j < 8; j++) {
        int col = cx.wn + j * 8 + cx.t * 2;
        #pragma unroll
        for (int i = 0; i < 2; i++) {
            int r0 = m0 + cx.wm + i * 16 + cx.g;
            int r1 = r0 + 8;
            if (r0 < M) *(__half2*)(C16 + (size_t)r0 * D + col)
                = __floats2half2_rn(acc[i][j][0], acc[i][j][1]);
            if (r1 < M) *(__half2*)(C16 + (size_t)r1 * D + col)
                = __floats2half2_rn(acc[i][j][2], acc[i][j][3]);
        }
    }
}

// ---------------------------------------------------------------------------
// Graph preprocessing: degree count + hierarchical exclusive scan + CSR fill
// ---------------------------------------------------------------------------
__global__ void deg_kernel(const int* __restrict__ dst, int e)
{
    int i = blockIdx.x * blockDim.x + threadIdx.x;
    if (i < e) atomicAdd(&d_deg[dst[i]], 1);
}

__global__ void scanA_kernel(int n)
{
    __shared__ int wsum[32];
    int i = blockIdx.x * 1024 + threadIdx.x;
    int lane = threadIdx.x & 31, w = threadIdx.x >> 5;
    int v = (i < n) ? d_deg[i] : 0;
    #pragma unroll
    for (int off = 16; off; off >>= 1)
        v += __shfl_xor_sync(0xffffffffu, v, off);
    if (lane == 0) wsum[w] = v;
    __syncthreads();
    if (w == 0) {
        int s = wsum[lane];
        #pragma unroll
        for (int off = 16; off; off >>= 1)
            s += __shfl_xor_sync(0xffffffffu, s, off);
        if (lane == 0) d_part[blockIdx.x] = s;
    }
}

__global__ void scanB_kernel(int nb, int n)
{
    int run = 0;
    for (int i = 0; i < nb; i++) {
        int v = d_part[i];
        d_part[i] = run;
        run += v;
    }
    d_row[n] = run;
}

// scanC also computes log(deg)
__global__ void scanC_kernel(int n)
{
    __shared__ int wsum[32];
    int i = blockIdx.x * 1024 + threadIdx.x;
    int lane = threadIdx.x & 31, w = threadIdx.x >> 5;
    int v = (i < n) ? d_deg[i] : 0;
    int incl = v;
    #pragma unroll
    for (int off = 1; off < 32; off <<= 1) {
        int t = __shfl_up_sync(0xffffffffu, incl, off);
        if (lane >= off) incl += t;
    }
    if (lane == 31) wsum[w] = incl;
    __syncthreads();
    if (w == 0) {
        int ws = wsum[lane];
        int wi = ws;
        #pragma unroll
        for (int off = 1; off < 32; off <<= 1) {
            int t = __shfl_up_sync(0xffffffffu, wi, off);
            if (lane >= off) wi += t;
        }
        wsum[lane] = wi - ws;
    }
    __syncthreads();
    int excl = d_part[blockIdx.x] + wsum[w] + (incl - v);
    if (i < n) {
        d_row[i] = excl;
        d_cur[i] = excl;
        d_log[i] = logf((float)v);
    }
}

__global__ void fill_kernel(const int* __restrict__ src,
                            const int* __restrict__ dst, int e)
{
    int i = blockIdx.x * blockDim.x + threadIdx.x;
    if (i >= e) return;
    int p = atomicAdd(&d_cur[dst[i]], 1);
    d_csr[p] = src[i];
}

// ---------------------------------------------------------------------------
// 16-lane row gather: lane sub (0..15) owns dims [8*sub, 8*sub+8), LDG.128
// ---------------------------------------------------------------------------
__device__ __forceinline__ void gather_h8(const __half* __restrict__ base,
                                          int node, int sub, float* f)
{
    uint4 r = *(const uint4*)(base + (size_t)node * D + sub * 8);
    const __half2* h = (const __half2*)&r;
    #pragma unroll
    for (int i = 0; i < 4; i++) {
        float2 t = __half22float2(h[i]);
        f[2*i]   = t.x;
        f[2*i+1] = t.y;
    }
}

// ---------------------------------------------------------------------------
// Attention + edge softmax, single pass (no max subtraction; logits provably
// small). One warp per destination node, half-warp per edge.
// ---------------------------------------------------------------------------
__global__ void attn_kernel(const float* __restrict__ attnw, int n)
{
    int warp = (blockIdx.x * blockDim.x + threadIdx.x) >> 5;
    int lane = threadIdx.x & 31;
    if (warp >= n) return;
    int node = warp;
    int half = lane >> 4;
    int sub  = lane & 15;
    int h    = sub >> 1;

    float ftv[8], aw[8];
    gather_h8(d_ft16, node, sub, ftv);
    {
        float4 a0 = *(const float4*)(attnw + sub * 8);
        float4 a1 = *(const float4*)(attnw + sub * 8 + 4);
        aw[0]=a0.x; aw[1]=a0.y; aw[2]=a0.z; aw[3]=a0.w;
        aw[4]=a1.x; aw[5]=a1.y; aw[6]=a1.z; aw[7]=a1.w;
    }
    float li = d_log[node] * (1.f / HDIM);
    int begin = d_row[node], end = d_row[node + 1];

    float ssum = 0.f;
    int s2 = begin;
    for (; s2 + 3 < end; s2 += 4) {
        int e0 = s2 + half;
        int e1 = s2 + 2 + half;
        int sn0 = d_csr[e0], sn1 = d_csr[e1];
        float f0[8], f1[8];
        gather_h8(d_fh16, sn0, sub, f0);
        gather_h8(d_fh16, sn1, sub, f1);
        float p0 = 0.f, p1 = 0.f;
        #pragma unroll
        for (int j = 0; j < 8; j++) {
            float q0 = f0[j] * ftv[j]; q0 = q0 > 0.f ? q0 : SLOPE * q0;
            float q1 = f1[j] * ftv[j]; q1 = q1 > 0.f ? q1 : SLOPE * q1;
            p0 += q0 * aw[j];
            p1 += q1 * aw[j];
        }
        p0 += __shfl_xor_sync(0xffffffffu, p0, 1);
        p1 += __shfl_xor_sync(0xffffffffu, p1, 1);
        if ((sub & 1) == 0) {
            float x0 = expf(p0 * li);
            float x1 = expf(p1 * li);
            d_att16[(size_t)e0 * NHEAD + h] = __float2half_rn(x0);
            d_att16[(size_t)e1 * NHEAD + h] = __float2half_rn(x1);
            ssum += x0 + x1;
        }
    }
    for (; s2 < end; s2 += 2) {
        int e = s2 + half;
        bool vld = e < end;
        int sn = vld ? d_csr[e] : node;
        float f[8];
        gather_h8(d_fh16, sn, sub, f);
        float p = 0.f;
        #pragma unroll
        for (int j = 0; j < 8; j++) {
            float q = f[j] * ftv[j]; q = q > 0.f ? q : SLOPE * q;
            p += q * aw[j];
        }
        p += __shfl_xor_sync(0xffffffffu, p, 1);
        if (vld && (sub & 1) == 0) {
            float x = expf(p * li);
            d_att16[(size_t)e * NHEAD + h] = __float2half_rn(x);
            ssum += x;
        }
    }
    ssum += __shfl_xor_sync(0xffffffffu, ssum, 16);
    if ((sub & 1) == 0 && half == 0)
        d_inv[(size_t)node * NHEAD + h] = (1.f - ALPHA) / ssum;
}

// ---------------------------------------------------------------------------
// Hop aggregation: half-warp per edge, 8 edges per warp-iter (4 per half),
// direct csr loads, LDG.128 gathers.
// ---------------------------------------------------------------------------
__device__ __forceinline__ void hop_agg(const __half* __restrict__ fin,
                                        int node, int half, int sub, int h,
                                        float* o)
{
    int begin = d_row[node], end = d_row[node + 1];
    float acc[8];
    #pragma unroll
    for (int j = 0; j < 8; j++) acc[j] = 0.f;

    int s2 = begin;
    for (; s2 + 7 < end; s2 += 8) {
        int e0 = s2 + half;
        int e1 = s2 + 2 + half;
        int e2 = s2 + 4 + half;
        int e3 = s2 + 6 + half;
        int sn0 = d_csr[e0], sn1 = d_csr[e1];
        int sn2 = d_csr[e2], sn3 = d_csr[e3];
        float a0 = __half2float(d_att16[(size_t)e0 * NHEAD + h]);
        float a1 = __half2float(d_att16[(size_t)e1 * NHEAD + h]);
        float a2 = __half2float(d_att16[(size_t)e2 * NHEAD + h]);
        float a3 = __half2float(d_att16[(size_t)e3 * NHEAD + h]);
        float f0[8], f1[8], f2[8], f3[8];
        gather_h8(fin, sn0, sub, f0);
        gather_h8(fin, sn1, sub, f1);
        gather_h8(fin, sn2, sub, f2);
        gather_h8(fin, sn3, sub, f3);
        #pragma unroll
        for (int j = 0; j < 8; j++)
            acc[j] += (a0 * f0[j] + a1 * f1[j]) + (a2 * f2[j] + a3 * f3[j]);
    }
    for (; s2 + 3 < end; s2 += 4) {
        int e0 = s2 + half;
        int e1 = s2 + 2 + half;
        int sn0 = d_csr[e0], sn1 = d_csr[e1];
        float a0 = __half2float(d_att16[(size_t)e0 * NHEAD + h]);
        float a1 = __half2float(d_att16[(size_t)e1 * NHEAD + h]);
        float f0[8], f1[8];
        gather_h8(fin, sn0, sub, f0);
        gather_h8(fin, sn1, sub, f1);
        #pragma unroll
        for (int j = 0; j < 8; j++)
            acc[j] += a0 * f0[j] + a1 * f1[j];
    }
    for (; s2 < end; s2 += 2) {
        int e = s2 + half;
        bool vld = e < end;
        int sn = vld ? d_csr[e] : node;
        float a = vld ? __half2float(d_att16[(size_t)e * NHEAD + h]) : 0.f;
        float f[8];
        gather_h8(fin, sn, sub, f);
        #pragma unroll
        for (int j = 0; j < 8; j++)
            acc[j] += a * f[j];
    }
    #pragma unroll
    for (int j = 0; j < 8; j++)
        acc[j] += __shfl_xor_sync(0xffffffffu, acc[j], 16);

    float inv = d_inv[(size_t)node * NHEAD + h];   // includes (1-alpha)
    float fe[8];
    gather_h8(d_fe16, node, sub, fe);
    #pragma unroll
    for (int j = 0; j < 8; j++)
        o[j] = inv * acc[j] + ALPHA * fe[j];
}

// intermediate hop: write fp16 (half 0 lanes store uint4)
__global__ void hop_kernel(const __half* __restrict__ fin,
                           __half* __restrict__ fout, int n)
{
    int warp = (blockIdx.x * blockDim.x + threadIdx.x) >> 5;
    int lane = threadIdx.x & 31;
    if (warp >= n) return;
    int half = lane >> 4, sub = lane & 15, h = sub >> 1;
    float o[8];
    hop_agg(fin, warp, half, sub, h, o);
    if (half == 0) {
        uint4 out;
        __half2* ph = (__half2*)&out;
        ph[0] = __floats2half2_rn(o[0], o[1]);
        ph[1] = __floats2half2_rn(o[2], o[3]);
        ph[2] = __floats2half2_rn(o[4], o[5]);
        ph[3] = __floats2half2_rn(o[6], o[7]);
        *(uint4*)(fout + (size_t)warp * D + sub * 8) = out;
    }
}

// last hop fused with residual + LN2: rst = o + feat (fp16 store);
// x2 = LN(rst) (fp16). LN computed on fp32 r values.
__global__ void hop_last_kernel(const __half* __restrict__ fin,
                                const float* __restrict__ feat,
                                const float* __restrict__ g,
                                const float* __restrict__ b, int n)
{
    int warp = (blockIdx.x * blockDim.x + threadIdx.x) >> 5;
    int lane = threadIdx.x & 31;
    if (warp >= n) return;
    int half = lane >> 4, sub = lane & 15, h = sub >> 1;
    float o[8];
    hop_agg(fin, warp, half, sub, h, o);

    float r[8];
    {
        float4 t0 = *(const float4*)(feat + (size_t)warp * D + sub * 8);
        float4 t1 = *(const float4*)(feat + (size_t)warp * D + sub * 8 + 4);
        r[0]=o[0]+t0.x; r[1]=o[1]+t0.y; r[2]=o[2]+t0.z; r[3]=o[3]+t0.w;
        r[4]=o[4]+t1.x; r[5]=o[5]+t1.y; r[6]=o[6]+t1.z; r[7]=o[7]+t1.w;
    }
    if (half == 0) {
        uint4 rout;
        __half2* pr = (__half2*)&rout;
        pr[0] = __floats2half2_rn(r[0], r[1]);
        pr[1] = __floats2half2_rn(r[2], r[3]);
        pr[2] = __floats2half2_rn(r[4], r[5]);
        pr[3] = __floats2half2_rn(r[6], r[7]);
        *(uint4*)(d_rst16 + (size_t)warp * D + sub * 8) = rout;
    }
    float s = 0.f, ss = 0.f;
    #pragma unroll
    for (int j = 0; j < 8; j++) { s += r[j]; ss += r[j] * r[j]; }
    #pragma unroll
    for (int off = 8; off; off >>= 1) {
        s  += __shfl_xor_sync(0xffffffffu, s,  off);
        ss += __shfl_xor_sync(0xffffffffu, ss, off);
    }
    float mean = s * (1.f / D);
    float var  = ss * (1.f / D) - mean * mean;
    float rstd = rsqrtf(var + LNEPS);
    if (half == 0) {
        float4 g0 = *(const float4*)(g + sub * 8);
        float4 g1 = *(const float4*)(g + sub * 8 + 4);
        float4 b0 = *(const float4*)(b + sub * 8);
        float4 b1 = *(const float4*)(b + sub * 8 + 4);
        uint4 out;
        __half2* ph = (__half2*)&out;
        ph[0] = __floats2half2_rn((r[0]-mean)*rstd*g0.x + b0.x,
                                  (r[1]-mean)*rstd*g0.y + b0.y);
        ph[1] = __floats2half2_rn((r[2]-mean)*rstd*g0.z + b0.z,
                                  (r[3]-mean)*rstd*g0.w + b0.w);
        ph[2] = __floats2half2_rn((r[4]-mean)*rstd*g1.x + b1.x,
                                  (r[5]-mean)*rstd*g1.y + b1.y);
        ph[3] = __floats2half2_rn((r[6]-mean)*rstd*g1.z + b1.z,
                                  (r[7]-mean)*rstd*g1.w + b1.w);
        *(uint4*)(d_x216 + (size_t)warp * D + sub * 8) = out;
    }
}

// ---------------------------------------------------------------------------
// Host launch: CSR build chain forked onto a side stream, overlapped with
// LN1 + projections; joined before attn.
// ---------------------------------------------------------------------------
extern "C" void kernel_launch(void* const* d_in, const int* in_sizes, int n_in,
                              void* d_out, int out_size)
{
    const float* feat  = (const float*)d_in[0];
    const int*   src   = (const int*)  d_in[1];
    const int*   dst   = (const int*)  d_in[2];
    const float* ln1_g = (const float*)d_in[3];
    const float* ln1_b = (const float*)d_in[4];
    const float* W_head= (const float*)d_in[5];
    const float* W_tail= (const float*)d_in[6];
    const float* W_ent = (const float*)d_in[7];
    const float* attnw = (const float*)d_in[8];
    const float* ln2_g = (const float*)d_in[9];
    const float* ln2_b = (const float*)d_in[10];
    const float* W_ff1 = (const float*)d_in[11];
    const float* b_ff1 = (const float*)d_in[12];
    const float* W_ff2 = (const float*)d_in[13];
    const float* b_ff2 = (const float*)d_in[14];

    int n = in_sizes[0] / D;
    int e = in_sizes[1];

    __half *p_h16, *p_g0, *p_g1, *p_fe16, *p_rst16, *p_x216, *p_y116;
    int *p_deg;
    cudaGetSymbolAddress((void**)&p_h16,   d_h16);
    cudaGetSymbolAddress((void**)&p_g0,    d_g0);
    cudaGetSymbolAddress((void**)&p_g1,    d_g1);
    cudaGetSymbolAddress((void**)&p_rst16, d_rst16);
    cudaGetSymbolAddress((void**)&p_x216,  d_x216);
    cudaGetSymbolAddress((void**)&p_y116,  d_y116);
    cudaGetSymbolAddress((void**)&p_deg,   d_deg);
    cudaGetSymbolAddress((void**)&p_fe16,  d_fe16);

    // One-time stream/event creation (host resources, not device memory).
    static cudaStream_t s_side = nullptr;
    static cudaEvent_t  ev_fork = nullptr, ev_join = nullptr;
    if (s_side == nullptr) {
        cudaStreamCreateWithFlags(&s_side, cudaStreamNonBlocking);
        cudaEventCreateWithFlags(&ev_fork, cudaEventDisableTiming);
        cudaEventCreateWithFlags(&ev_join, cudaEventDisableTiming);
    }

    const int TPB = 256;
    int rowBlocks  = (n * 32 + TPB - 1) / TPB;
    int edgeBlocks = (e + TPB - 1) / TPB;
    int nb = (n + 1023) / 1024;

    // Fork side stream off the main (capture) stream.
    cudaEventRecord(ev_fork, 0);
    cudaStreamWaitEvent(s_side, ev_fork, 0);

    // Side stream: CSR build chain (independent of LN1/projections).
    cudaMemsetAsync(p_deg, 0, (size_t)n * sizeof(int), s_side);
    deg_kernel<<<edgeBlocks, TPB, 0, s_side>>>(dst, e);
    scanA_kernel<<<nb, 1024, 0, s_side>>>(n);
    scanB_kernel<<<1, 1, 0, s_side>>>(nb, n);
    scanC_kernel<<<nb, 1024, 0, s_side>>>(n);
    fill_kernel<<<edgeBlocks, TPB, 0, s_side>>>(src, dst, e);
    cudaEventRecord(ev_join, s_side);

    // Main stream: LN1 (fp16 out) + projections (fp16 A, concurrent with CSR).
    ln_kernel<<<rowBlocks, TPB>>>(feat, ln1_g, ln1_b, p_h16, n);
    dim3 gproj(1, (n + 127) / 128, 3);
    proj_gemm_kernel<<<gproj, 256>>>(p_h16, W_head, W_tail, W_ent, n);

    // Join: attn needs both CSR and projections.
    cudaStreamWaitEvent(0, ev_join, 0);

    // 4. attention logits + edge softmax (single pass)
    attn_kernel<<<rowBlocks, TPB>>>(attnw, n);

    // 5. diffusion: 5 hops (fp16 ping-pong), last hop fused with residual+LN2
    hop_kernel<<<rowBlocks, TPB>>>(p_fe16, p_g0, n);
    hop_kernel<<<rowBlocks, TPB>>>(p_g0, p_g1, n);
    hop_kernel<<<rowBlocks, TPB>>>(p_g1, p_g0, n);
    hop_kernel<<<rowBlocks, TPB>>>(p_g0, p_g1, n);
    hop_last_kernel<<<rowBlocks, TPB>>>(p_g1, feat, ln2_g, ln2_b, n);

    // 6. FFN (fp16 tensor cores, fp16 intermediate + fp16 x2 + fp16 rst add)
    dim3 gff1(DFF / 128, (n + 127) / 128);
    mma_gemm_kernel<true, true, false, true, __half><<<gff1, 256>>>(
        p_x216, W_ff1, b_ff1, nullptr, p_y116, n, DFF, D);
    dim3 gff2(D / 128, (n + 127) / 128);
    mma_gemm_kernel<false, true, true, false, __half><<<gff2, 256>>>(
        p_y116, W_ff2, b_ff2, p_rst16, d_out, n, D, DFF);
}

// round 16
// speedup vs baseline: 1.0149x; 1.0086x over previous
#include <cuda_runtime.h>
#include <cuda_fp16.h>
#include <math.h>

// ---------------------------------------------------------------------------
// Problem constants (fixed shapes per reference)
// ---------------------------------------------------------------------------
#define MAXN 50048
#define MAXE 850048
#define D    128         // D_IN == D_OUT
#define DFF  512
#define NHEAD 8
#define HDIM 16
#define ALPHA 0.15f
#define SLOPE 0.2f
#define LNEPS 1e-5f

// weight fp16 cache offsets (elements)
#define WOFF_HEAD 0
#define WOFF_TAIL (D * D)
#define WOFF_ENT  (2 * D * D)
#define WOFF_FF1  (3 * D * D)
#define WOFF_FF2  (3 * D * D + DFF * D)
#define WTOTAL    (3 * D * D + 2 * DFF * D)

// ---------------------------------------------------------------------------
// Scratch (static device globals; no runtime allocation)
// ---------------------------------------------------------------------------
__device__ __half d_h16  [MAXN * D];    // LN1 output, fp16 (proj GEMM A input)
__device__ __half d_fh16 [MAXN * D];    // head proj, fp16 (gathered in attn)
__device__ __half d_ft16 [MAXN * D];    // tail proj, fp16 (node-local in attn)
__device__ __half d_fe16 [MAXN * D];    // ent proj, fp16 (gathered + alpha term)
__device__ __half d_g0   [MAXN * D];    // hop ping-pong (fp16)
__device__ __half d_g1   [MAXN * D];
__device__ __half d_rst16[MAXN * D];    // residual, fp16 (FFN2 add input)
__device__ __half d_x216 [MAXN * D];    // LN2 output, fp16 (FFN1 input)
__device__ __half d_y116 [MAXN * DFF];  // FFN intermediate, fp16
__device__ __half d_w16  [WTOTAL];      // fp16 weight cache (all 5 matrices)
__device__ __half d_att16[MAXE * NHEAD];   // fp16 exp weights (hop loop)
__device__ float  d_inv  [MAXN * NHEAD];
__device__ int    d_csr  [MAXE];
__device__ int    d_deg  [MAXN];
__device__ int    d_cur  [MAXN];
__device__ int    d_row  [MAXN + 1];
__device__ int    d_part [64];
__device__ float  d_log  [MAXN];

// ---------------------------------------------------------------------------
// Weight conversion: fp32 -> fp16 once per launch (rounding identical to the
// previous per-CTA smem-store conversion).
// ---------------------------------------------------------------------------
__global__ void wcvt_kernel(const float* __restrict__ Wh,
                            const float* __restrict__ Wt,
                            const float* __restrict__ We,
                            const float* __restrict__ Wf1,
                            const float* __restrict__ Wf2)
{
    int i = blockIdx.x * blockDim.x + threadIdx.x;
    if (i >= WTOTAL) return;
    float v;
    if      (i < WOFF_TAIL) v = Wh [i - WOFF_HEAD];
    else if (i < WOFF_ENT)  v = Wt [i - WOFF_TAIL];
    else if (i < WOFF_FF1)  v = We [i - WOFF_ENT];
    else if (i < WOFF_FF2)  v = Wf1[i - WOFF_FF1];
    else                    v = Wf2[i - WOFF_FF2];
    d_w16[i] = __float2half_rn(v);
}

// ---------------------------------------------------------------------------
// LayerNorm: one warp per row of 128 floats, fp16 output
// ---------------------------------------------------------------------------
__global__ void ln_kernel(const float* __restrict__ x,
                          const float* __restrict__ g,
                          const float* __restrict__ b,
                          __half* __restrict__ y, int n)
{
    int warp = (blockIdx.x * blockDim.x + threadIdx.x) >> 5;
    int lane = threadIdx.x & 31;
    if (warp >= n) return;
    const float4 v = *(const float4*)(x + (size_t)warp * D + lane * 4);
    float s  = v.x + v.y + v.z + v.w;
    float ss = v.x*v.x + v.y*v.y + v.z*v.z + v.w*v.w;
    #pragma unroll
    for (int off = 16; off; off >>= 1) {
        s  += __shfl_xor_sync(0xffffffffu, s,  off);
        ss += __shfl_xor_sync(0xffffffffu, ss, off);
    }
    float mean = s * (1.f / D);
    float var  = ss * (1.f / D) - mean * mean;
    float rstd = rsqrtf(var + LNEPS);
    const float4 gv = *(const float4*)(g + lane * 4);
    const float4 bv = *(const float4*)(b + lane * 4);
    uint2 out;
    __half2* ph = (__half2*)&out;
    ph[0] = __floats2half2_rn((v.x - mean) * rstd * gv.x + bv.x,
                              (v.y - mean) * rstd * gv.y + bv.y);
    ph[1] = __floats2half2_rn((v.z - mean) * rstd * gv.z + bv.z,
                              (v.w - mean) * rstd * gv.w + bv.w);
    *(uint2*)(y + (size_t)warp * D + lane * 4) = out;
}

// ---------------------------------------------------------------------------
// FP16 tensor-core GEMM machinery (mma.m16n8k16, fp32 accumulate)
// Both A and B fp16 in global; raw uint2 loads, zero conversion in mainloop.
// ---------------------------------------------------------------------------
#define PADH 12

__device__ __forceinline__ void mma_f16(float* c, const __half2* a, const __half2* b) {
    asm volatile(
        "mma.sync.aligned.m16n8k16.row.col.f32.f16.f16.f32 "
        "{%0,%1,%2,%3}, {%4,%5,%6,%7}, {%8,%9}, {%0,%1,%2,%3};\n"
        : "+f"(c[0]), "+f"(c[1]), "+f"(c[2]), "+f"(c[3])
        : "r"(*(const unsigned*)&a[0]), "r"(*(const unsigned*)&a[1]),
          "r"(*(const unsigned*)&a[2]), "r"(*(const unsigned*)&a[3]),
          "r"(*(const unsigned*)&b[0]), "r"(*(const unsigned*)&b[1]));
}

struct MmaCtx {
    const __half *Ap0, *Ap1, *Bp0, *Bp1;
    bool av0, av1;
    int grow, gc2, wm, wn, g, t;
};

__device__ __forceinline__ MmaCtx make_ctx(const __half* A, const __half* B,
                                           int m0, int n0, int M, int K,
                                           int tid)
{
    MmaCtx cx;
    int lane = tid & 31, wid = tid >> 5;
    cx.grow = tid >> 2;
    int gcol = (tid & 3) * 4;       // 4 halves = 8 bytes (uint2)
    cx.gc2  = (tid & 3) * 2;
    cx.av0 = (m0 + cx.grow)      < M;
    cx.av1 = (m0 + cx.grow + 64) < M;
    cx.Ap0 = A + (size_t)(m0 + cx.grow)      * K + gcol;
    cx.Ap1 = A + (size_t)(m0 + cx.grow + 64) * K + gcol;
    cx.Bp0 = B + (size_t)(n0 + cx.grow)      * K + gcol;
    cx.Bp1 = B + (size_t)(n0 + cx.grow + 64) * K + gcol;
    cx.wm = (wid & 3) * 32;
    cx.wn = (wid >> 2) * 64;
    cx.g = lane >> 2;
    cx.t = lane & 3;
    return cx;
}

__device__ __forceinline__ uint2 ldh4(const __half* p) {
    return *(const uint2*)p;
}

__device__ __forceinline__ void st_raw(__half2* s, int row, int c2, uint2 r) {
    s[row * PADH + c2]     = *(__half2*)&r.x;
    s[row * PADH + c2 + 1] = *(__half2*)&r.y;
}

template<typename AccT>
__device__ __forceinline__ void mma_mainloop(
    const MmaCtx& cx, int K, __half2 (*As)[128 * PADH], __half2 (*Bs)[128 * PADH],
    AccT& acc)
{
    const uint2 z2 = make_uint2(0u, 0u);
    {
        uint2 a0 = cx.av0 ? ldh4(cx.Ap0) : z2;
        uint2 a1 = cx.av1 ? ldh4(cx.Ap1) : z2;
        uint2 b0 = ldh4(cx.Bp0);
        uint2 b1 = ldh4(cx.Bp1);
        st_raw(As[0], cx.grow,      cx.gc2, a0);
        st_raw(As[0], cx.grow + 64, cx.gc2, a1);
        st_raw(Bs[0], cx.grow,      cx.gc2, b0);
        st_raw(Bs[0], cx.grow + 64, cx.gc2, b1);
    }
    __syncthreads();

    int nk = K >> 4;
    for (int it = 0; it < nk; ++it) {
        int buf = it & 1;
        bool more = (it + 1) < nk;
        uint2 na0, na1, nb0, nb1;
        if (more) {
            int ko = (it + 1) * 16;
            na0 = cx.av0 ? ldh4(cx.Ap0 + ko) : z2;
            na1 = cx.av1 ? ldh4(cx.Ap1 + ko) : z2;
            nb0 = ldh4(cx.Bp0 + ko);
            nb1 = ldh4(cx.Bp1 + ko);
        }
        const __half2* as = As[buf];
        const __half2* bs = Bs[buf];
        {
            __half2 afr[2][4];
            #pragma unroll
            for (int i = 0; i < 2; i++) {
                int r0 = (cx.wm + i * 16 + cx.g) * PADH;
                int r8 = (cx.wm + i * 16 + 8 + cx.g) * PADH;
                afr[i][0] = as[r0 + cx.t];
                afr[i][1] = as[r8 + cx.t];
                afr[i][2] = as[r0 + cx.t + 4];
                afr[i][3] = as[r8 + cx.t + 4];
            }
            #pragma unroll
            for (int j = 0; j < 8; j++) {
                int nb = (cx.wn + j * 8 + cx.g) * PADH + cx.t;
                __half2 bfr[2];
                bfr[0] = bs[nb];
                bfr[1] = bs[nb + 4];
                mma_f16(acc[0][j], afr[0], bfr);
                mma_f16(acc[1][j], afr[1], bfr);
            }
        }
        if (more) {
            int nbuf = buf ^ 1;
            st_raw(As[nbuf], cx.grow,      cx.gc2, na0);
            st_raw(As[nbuf], cx.grow + 64, cx.gc2, na1);
            st_raw(Bs[nbuf], cx.grow,      cx.gc2, nb0);
            st_raw(Bs[nbuf], cx.grow + 64, cx.gc2, nb1);
        }
        __syncthreads();
    }
}

// ---------------------------------------------------------------------------
// Generic GEMM: C[M,Nc] = A @ B^T (+bias, +relu, +add[fp16]); A,B fp16
// ---------------------------------------------------------------------------
template<bool RELU, bool HAS_BIAS, bool HAS_ADD, bool OUT_HALF>
__global__ void __launch_bounds__(256)
mma_gemm_kernel(const __half* __restrict__ A,
                const __half* __restrict__ B,
                const float* __restrict__ bias,
                const __half* __restrict__ add,
                void* __restrict__ Cv,
                int M, int Nc, int K)
{
    __shared__ __half2 As[2][128 * PADH];
    __shared__ __half2 Bs[2][128 * PADH];
    int tid = threadIdx.x;
    int m0 = blockIdx.y * 128;
    int n0 = blockIdx.x * 128;
    MmaCtx cx = make_ctx(A, B, m0, n0, M, K, tid);

    float acc[2][8][4];
    #pragma unroll
    for (int i = 0; i < 2; i++)
        #pragma unroll
        for (int j = 0; j < 8; j++)
            #pragma unroll
            for (int q = 0; q < 4; q++) acc[i][j][q] = 0.f;

    mma_mainloop(cx, K, As, Bs, acc);

    #pragma unroll
    for (int j = 0; j < 8; j++) {
        int col = n0 + cx.wn + j * 8 + cx.t * 2;
        float bx = 0.f, by = 0.f;
        if (HAS_BIAS) { bx = bias[col]; by = bias[col + 1]; }
        #pragma unroll
        for (int i = 0; i < 2; i++) {
            int r0 = m0 + cx.wm + i * 16 + cx.g;
            int r1 = r0 + 8;
            float2 o0, o1;
            o0.x = acc[i][j][0] + bx; o0.y = acc[i][j][1] + by;
            o1.x = acc[i][j][2] + bx; o1.y = acc[i][j][3] + by;
            if (RELU) {
                o0.x = fmaxf(o0.x, 0.f); o0.y = fmaxf(o0.y, 0.f);
                o1.x = fmaxf(o1.x, 0.f); o1.y = fmaxf(o1.y, 0.f);
            }
            if (r0 < M) {
                if (HAS_ADD) {
                    float2 ad = __half22float2(*(const __half2*)(add + (size_t)r0 * Nc + col));
                    o0.x += ad.x; o0.y += ad.y;
                }
                if (OUT_HALF)
                    *(__half2*)((__half*)Cv + (size_t)r0 * Nc + col) = __floats2half2_rn(o0.x, o0.y);
                else
                    *(float2*)((float*)Cv + (size_t)r0 * Nc + col) = o0;
            }
            if (r1 < M) {
                if (HAS_ADD) {
                    float2 ad = __half22float2(*(const __half2*)(add + (size_t)r1 * Nc + col));
                    o1.x += ad.x; o1.y += ad.y;
                }
                if (OUT_HALF)
                    *(__half2*)((__half*)Cv + (size_t)r1 * Nc + col) = __floats2half2_rn(o1.x, o1.y);
                else
                    *(float2*)((float*)Cv + (size_t)r1 * Nc + col) = o1;
            }
        }
    }
}

// ---------------------------------------------------------------------------
// Fused projection GEMM: blockIdx.z selects {W_head->fh16, W_tail->ft16, W_ent->fe16}
// ---------------------------------------------------------------------------
__global__ void __launch_bounds__(256)
proj_gemm_kernel(const __half* __restrict__ A, int M)
{
    __shared__ __half2 As[2][128 * PADH];
    __shared__ __half2 Bs[2][128 * PADH];
    int tid = threadIdx.x;
    int z = blockIdx.z;
    int m0 = blockIdx.y * 128;
    const __half* B = d_w16 + ((z == 0) ? WOFF_HEAD : (z == 1) ? WOFF_TAIL : WOFF_ENT);
    MmaCtx cx = make_ctx(A, B, m0, 0, M, D, tid);

    float acc[2][8][4];
    #pragma unroll
    for (int i = 0; i < 2; i++)
        #pragma unroll
        for (int j = 0; j < 8; j++)
            #pragma unroll
            for (int q = 0; q < 4; q++) acc[i][j][q] = 0.f;

    mma_mainloop(cx, D, As, Bs, acc);

    __half* C16 = (z == 0) ? d_fh16 : (z == 1) ? d_ft16 : d_fe16;
    #pragma unroll
    for (int j = 0; j < 8; j++) {
        int col = cx.wn + j * 8 + cx.t * 2;
        #pragma unroll
        for (int i = 0; i < 2; i++) {
            int r0 = m0 + cx.wm + i * 16 + cx.g;
            int r1 = r0 + 8;
            if (r0 < M) *(__half2*)(C16 + (size_t)r0 * D + col)
                = __floats2half2_rn(acc[i][j][0], acc[i][j][1]);
            if (r1 < M) *(__half2*)(C16 + (size_t)r1 * D + col)
                = __floats2half2_rn(acc[i][j][2], acc[i][j][3]);
        }
    }
}

// ---------------------------------------------------------------------------
// Graph preprocessing: degree count + hierarchical exclusive scan + CSR fill
// ---------------------------------------------------------------------------
__global__ void deg_kernel(const int* __restrict__ dst, int e)
{
    int i = blockIdx.x * blockDim.x + threadIdx.x;
    if (i < e) atomicAdd(&d_deg[dst[i]], 1);
}

__global__ void scanA_kernel(int n)
{
    __shared__ int wsum[32];
    int i = blockIdx.x * 1024 + threadIdx.x;
    int lane = threadIdx.x & 31, w = threadIdx.x >> 5;
    int v = (i < n) ? d_deg[i] : 0;
    #pragma unroll
    for (int off = 16; off; off >>= 1)
        v += __shfl_xor_sync(0xffffffffu, v, off);
    if (lane == 0) wsum[w] = v;
    __syncthreads();
    if (w == 0) {
        int s = wsum[lane];
        #pragma unroll
        for (int off = 16; off; off >>= 1)
            s += __shfl_xor_sync(0xffffffffu, s, off);
        if (lane == 0) d_part[blockIdx.x] = s;
    }
}

__global__ void scanB_kernel(int nb, int n)
{
    int run = 0;
    for (int i = 0; i < nb; i++) {
        int v = d_part[i];
        d_part[i] = run;
        run += v;
    }
    d_row[n] = run;
}

// scanC also computes log(deg)
__global__ void scanC_kernel(int n)
{
    __shared__ int wsum[32];
    int i = blockIdx.x * 1024 + threadIdx.x;
    int lane = threadIdx.x & 31, w = threadIdx.x >> 5;
    int v = (i < n) ? d_deg[i] : 0;
    int incl = v;
    #pragma unroll
    for (int off = 1; off < 32; off <<= 1) {
        int t = __shfl_up_sync(0xffffffffu, incl, off);
        if (lane >= off) incl += t;
    }
    if (lane == 31) wsum[w] = incl;
    __syncthreads();
    if (w == 0) {
        int ws = wsum[lane];
        int wi = ws;
        #pragma unroll
        for (int off = 1; off < 32; off <<= 1) {
            int t = __shfl_up_sync(0xffffffffu, wi, off);
            if (lane >= off) wi += t;
        }
        wsum[lane] = wi - ws;
    }
    __syncthreads();
    int excl = d_part[blockIdx.x] + wsum[w] + (incl - v);
    if (i < n) {
        d_row[i] = excl;
        d_cur[i] = excl;
        d_log[i] = logf((float)v);
    }
}

__global__ void fill_kernel(const int* __restrict__ src,
                            const int* __restrict__ dst, int e)
{
    int i = blockIdx.x * blockDim.x + threadIdx.x;
    if (i >= e) return;
    int p = atomicAdd(&d_cur[dst[i]], 1);
    d_csr[p] = src[i];
}

// ---------------------------------------------------------------------------
// 16-lane row gather: lane sub (0..15) owns dims [8*sub, 8*sub+8), LDG.128
// ---------------------------------------------------------------------------
__device__ __forceinline__ void gather_h8(const __half* __restrict__ base,
                                          int node, int sub, float* f)
{
    uint4 r = *(const uint4*)(base + (size_t)node * D + sub * 8);
    const __half2* h = (const __half2*)&r;
    #pragma unroll
    for (int i = 0; i < 4; i++) {
        float2 t = __half22float2(h[i]);
        f[2*i]   = t.x;
        f[2*i+1] = t.y;
    }
}

// ---------------------------------------------------------------------------
// Attention + edge softmax, single pass (no max subtraction; logits provably
// small). One warp per destination node, half-warp per edge.
// ---------------------------------------------------------------------------
__global__ void attn_kernel(const float* __restrict__ attnw, int n)
{
    int warp = (blockIdx.x * blockDim.x + threadIdx.x) >> 5;
    int lane = threadIdx.x & 31;
    if (warp >= n) return;
    int node = warp;
    int half = lane >> 4;
    int sub  = lane & 15;
    int h    = sub >> 1;

    float ftv[8], aw[8];
    gather_h8(d_ft16, node, sub, ftv);
    {
        float4 a0 = *(const float4*)(attnw + sub * 8);
        float4 a1 = *(const float4*)(attnw + sub * 8 + 4);
        aw[0]=a0.x; aw[1]=a0.y; aw[2]=a0.z; aw[3]=a0.w;
        aw[4]=a1.x; aw[5]=a1.y; aw[6]=a1.z; aw[7]=a1.w;
    }
    float li = d_log[node] * (1.f / HDIM);
    int begin = d_row[node], end = d_row[node + 1];

    float ssum = 0.f;
    int s2 = begin;
    for (; s2 + 3 < end; s2 += 4) {
        int e0 = s2 + half;
        int e1 = s2 + 2 + half;
        int sn0 = d_csr[e0], sn1 = d_csr[e1];
        float f0[8], f1[8];
        gather_h8(d_fh16, sn0, sub, f0);
        gather_h8(d_fh16, sn1, sub, f1);
        float p0 = 0.f, p1 = 0.f;
        #pragma unroll
        for (int j = 0; j < 8; j++) {
            float q0 = f0[j] * ftv[j]; q0 = q0 > 0.f ? q0 : SLOPE * q0;
            float q1 = f1[j] * ftv[j]; q1 = q1 > 0.f ? q1 : SLOPE * q1;
            p0 += q0 * aw[j];
            p1 += q1 * aw[j];
        }
        p0 += __shfl_xor_sync(0xffffffffu, p0, 1);
        p1 += __shfl_xor_sync(0xffffffffu, p1, 1);
        if ((sub & 1) == 0) {
            float x0 = __expf(p0 * li);
            float x1 = __expf(p1 * li);
            d_att16[(size_t)e0 * NHEAD + h] = __float2half_rn(x0);
            d_att16[(size_t)e1 * NHEAD + h] = __float2half_rn(x1);
            ssum += x0 + x1;
        }
    }
    for (; s2 < end; s2 += 2) {
        int e = s2 + half;
        bool vld = e < end;
        int sn = vld ? d_csr[e] : node;
        float f[8];
        gather_h8(d_fh16, sn, sub, f);
        float p = 0.f;
        #pragma unroll
        for (int j = 0; j < 8; j++) {
            float q = f[j] * ftv[j]; q = q > 0.f ? q : SLOPE * q;
            p += q * aw[j];
        }
        p += __shfl_xor_sync(0xffffffffu, p, 1);
        if (vld && (sub & 1) == 0) {
            float x = __expf(p * li);
            d_att16[(size_t)e * NHEAD + h] = __float2half_rn(x);
            ssum += x;
        }
    }
    ssum += __shfl_xor_sync(0xffffffffu, ssum, 16);
    if ((sub & 1) == 0 && half == 0)
        d_inv[(size_t)node * NHEAD + h] = (1.f - ALPHA) / ssum;
}

// ---------------------------------------------------------------------------
// Hop aggregation: half-warp per edge, 8 edges per warp-iter (4 per half),
// direct csr loads, LDG.128 gathers.
// ---------------------------------------------------------------------------
__device__ __forceinline__ void hop_agg(const __half* __restrict__ fin,
                                        int node, int half, int sub, int h,
                                        float* o)
{
    int begin = d_row[node], end = d_row[node + 1];
    float acc[8];
    #pragma unroll
    for (int j = 0; j < 8; j++) acc[j] = 0.f;

    int s2 = begin;
    for (; s2 + 7 < end; s2 += 8) {
        int e0 = s2 + half;
        int e1 = s2 + 2 + half;
        int e2 = s2 + 4 + half;
        int e3 = s2 + 6 + half;
        int sn0 = d_csr[e0], sn1 = d_csr[e1];
        int sn2 = d_csr[e2], sn3 = d_csr[e3];
        float a0 = __half2float(d_att16[(size_t)e0 * NHEAD + h]);
        float a1 = __half2float(d_att16[(size_t)e1 * NHEAD + h]);
        float a2 = __half2float(d_att16[(size_t)e2 * NHEAD + h]);
        float a3 = __half2float(d_att16[(size_t)e3 * NHEAD + h]);
        float f0[8], f1[8], f2[8], f3[8];
        gather_h8(fin, sn0, sub, f0);
        gather_h8(fin, sn1, sub, f1);
        gather_h8(fin, sn2, sub, f2);
        gather_h8(fin, sn3, sub, f3);
        #pragma unroll
        for (int j = 0; j < 8; j++)
            acc[j] += (a0 * f0[j] + a1 * f1[j]) + (a2 * f2[j] + a3 * f3[j]);
    }
    for (; s2 + 3 < end; s2 += 4) {
        int e0 = s2 + half;
        int e1 = s2 + 2 + half;
        int sn0 = d_csr[e0], sn1 = d_csr[e1];
        float a0 = __half2float(d_att16[(size_t)e0 * NHEAD + h]);
        float a1 = __half2float(d_att16[(size_t)e1 * NHEAD + h]);
        float f0[8], f1[8];
        gather_h8(fin, sn0, sub, f0);
        gather_h8(fin, sn1, sub, f1);
        #pragma unroll
        for (int j = 0; j < 8; j++)
            acc[j] += a0 * f0[j] + a1 * f1[j];
    }
    for (; s2 < end; s2 += 2) {
        int e = s2 + half;
        bool vld = e < end;
        int sn = vld ? d_csr[e] : node;
        float a = vld ? __half2float(d_att16[(size_t)e * NHEAD + h]) : 0.f;
        float f[8];
        gather_h8(fin, sn, sub, f);
        #pragma unroll
        for (int j = 0; j < 8; j++)
            acc[j] += a * f[j];
    }
    #pragma unroll
    for (int j = 0; j < 8; j++)
        acc[j] += __shfl_xor_sync(0xffffffffu, acc[j], 16);

    float inv = d_inv[(size_t)node * NHEAD + h];   // includes (1-alpha)
    float fe[8];
    gather_h8(d_fe16, node, sub, fe);
    #pragma unroll
    for (int j = 0; j < 8; j++)
        o[j] = inv * acc[j] + ALPHA * fe[j];
}

// intermediate hop: write fp16 (half 0 lanes store uint4)
__global__ void hop_kernel(const __half* __restrict__ fin,
                           __half* __restrict__ fout, int n)
{
    int warp = (blockIdx.x * blockDim.x + threadIdx.x) >> 5;
    int lane = threadIdx.x & 31;
    if (warp >= n) return;
    int half = lane >> 4, sub = lane & 15, h = sub >> 1;
    float o[8];
    hop_agg(fin, warp, half, sub, h, o);
    if (half == 0) {
        uint4 out;
        __half2* ph = (__half2*)&out;
        ph[0] = __floats2half2_rn(o[0], o[1]);
        ph[1] = __floats2half2_rn(o[2], o[3]);
        ph[2] = __floats2half2_rn(o[4], o[5]);
        ph[3] = __floats2half2_rn(o[6], o[7]);
        *(uint4*)(fout + (size_t)warp * D + sub * 8) = out;
    }
}

// last hop fused with residual + LN2: rst = o + feat (fp16 store);
// x2 = LN(rst) (fp16). LN computed on fp32 r values.
__global__ void hop_last_kernel(const __half* __restrict__ fin,
                                const float* __restrict__ feat,
                                const float* __restrict__ g,
                                const float* __restrict__ b, int n)
{
    int warp = (blockIdx.x * blockDim.x + threadIdx.x) >> 5;
    int lane = threadIdx.x & 31;
    if (warp >= n) return;
    int half = lane >> 4, sub = lane & 15, h = sub >> 1;
    float o[8];
    hop_agg(fin, warp, half, sub, h, o);

    float r[8];
    {
        float4 t0 = *(const float4*)(feat + (size_t)warp * D + sub * 8);
        float4 t1 = *(const float4*)(feat + (size_t)warp * D + sub * 8 + 4);
        r[0]=o[0]+t0.x; r[1]=o[1]+t0.y; r[2]=o[2]+t0.z; r[3]=o[3]+t0.w;
        r[4]=o[4]+t1.x; r[5]=o[5]+t1.y; r[6]=o[6]+t1.z; r[7]=o[7]+t1.w;
    }
    if (half == 0) {
        uint4 rout;
        __half2* pr = (__half2*)&rout;
        pr[0] = __floats2half2_rn(r[0], r[1]);
        pr[1] = __floats2half2_rn(r[2], r[3]);
        pr[2] = __floats2half2_rn(r[4], r[5]);
        pr[3] = __floats2half2_rn(r[6], r[7]);
        *(uint4*)(d_rst16 + (size_t)warp * D + sub * 8) = rout;
    }
    float s = 0.f, ss = 0.f;
    #pragma unroll
    for (int j = 0; j < 8; j++) { s += r[j]; ss += r[j] * r[j]; }
    #pragma unroll
    for (int off = 8; off; off >>= 1) {
        s  += __shfl_xor_sync(0xffffffffu, s,  off);
        ss += __shfl_xor_sync(0xffffffffu, ss, off);
    }
    float mean = s * (1.f / D);
    float var  = ss * (1.f / D) - mean * mean;
    float rstd = rsqrtf(var + LNEPS);
    if (half == 0) {
        float4 g0 = *(const float4*)(g + sub * 8);
        float4 g1 = *(const float4*)(g + sub * 8 + 4);
        float4 b0 = *(const float4*)(b + sub * 8);
        float4 b1 = *(const float4*)(b + sub * 8 + 4);
        uint4 out;
        __half2* ph = (__half2*)&out;
        ph[0] = __floats2half2_rn((r[0]-mean)*rstd*g0.x + b0.x,
                                  (r[1]-mean)*rstd*g0.y + b0.y);
        ph[1] = __floats2half2_rn((r[2]-mean)*rstd*g0.z + b0.z,
                                  (r[3]-mean)*rstd*g0.w + b0.w);
        ph[2] = __floats2half2_rn((r[4]-mean)*rstd*g1.x + b1.x,
                                  (r[5]-mean)*rstd*g1.y + b1.y);
        ph[3] = __floats2half2_rn((r[6]-mean)*rstd*g1.z + b1.z,
                                  (r[7]-mean)*rstd*g1.w + b1.w);
        *(uint4*)(d_x216 + (size_t)warp * D + sub * 8) = out;
    }
}

// ---------------------------------------------------------------------------
// Host launch: CSR build chain forked onto a side stream, overlapped with
// weight-cvt + LN1 + projections; joined before attn.
// ---------------------------------------------------------------------------
extern "C" void kernel_launch(void* const* d_in, const int* in_sizes, int n_in,
                              void* d_out, int out_size)
{
    const float* feat  = (const float*)d_in[0];
    const int*   src   = (const int*)  d_in[1];
    const int*   dst   = (const int*)  d_in[2];
    const float* ln1_g = (const float*)d_in[3];
    const float* ln1_b = (const float*)d_in[4];
    const float* W_head= (const float*)d_in[5];
    const float* W_tail= (const float*)d_in[6];
    const float* W_ent = (const float*)d_in[7];
    const float* attnw = (const float*)d_in[8];
    const float* ln2_g = (const float*)d_in[9];
    const float* ln2_b = (const float*)d_in[10];
    const float* W_ff1 = (const float*)d_in[11];
    const float* b_ff1 = (const float*)d_in[12];
    const float* W_ff2 = (const float*)d_in[13];
    const float* b_ff2 = (const float*)d_in[14];

    int n = in_sizes[0] / D;
    int e = in_sizes[1];

    __half *p_h16, *p_g0, *p_g1, *p_fe16, *p_rst16, *p_x216, *p_y116, *p_w16;
    int *p_deg;
    cudaGetSymbolAddress((void**)&p_h16,   d_h16);
    cudaGetSymbolAddress((void**)&p_g0,    d_g0);
    cudaGetSymbolAddress((void**)&p_g1,    d_g1);
    cudaGetSymbolAddress((void**)&p_rst16, d_rst16);
    cudaGetSymbolAddress((void**)&p_x216,  d_x216);
    cudaGetSymbolAddress((void**)&p_y116,  d_y116);
    cudaGetSymbolAddress((void**)&p_deg,   d_deg);
    cudaGetSymbolAddress((void**)&p_fe16,  d_fe16);
    cudaGetSymbolAddress((void**)&p_w16,   d_w16);

    // One-time stream/event creation (host resources, not device memory).
    static cudaStream_t s_side = nullptr;
    static cudaEvent_t  ev_fork = nullptr, ev_join = nullptr;
    if (s_side == nullptr) {
        cudaStreamCreateWithFlags(&s_side, cudaStreamNonBlocking);
        cudaEventCreateWithFlags(&ev_fork, cudaEventDisableTiming);
        cudaEventCreateWithFlags(&ev_join, cudaEventDisableTiming);
    }

    const int TPB = 256;
    int rowBlocks  = (n * 32 + TPB - 1) / TPB;
    int edgeBlocks = (e + TPB - 1) / TPB;
    int nb = (n + 1023) / 1024;

    // Fork side stream off the main (capture) stream.
    cudaEventRecord(ev_fork, 0);
    cudaStreamWaitEvent(s_side, ev_fork, 0);

    // Side stream: CSR build chain (independent of LN1/projections).
    cudaMemsetAsync(p_deg, 0, (size_t)n * sizeof(int), s_side);
    deg_kernel<<<edgeBlocks, TPB, 0, s_side>>>(dst, e);
    scanA_kernel<<<nb, 1024, 0, s_side>>>(n);
    scanB_kernel<<<1, 1, 0, s_side>>>(nb, n);
    scanC_kernel<<<nb, 1024, 0, s_side>>>(n);
    fill_kernel<<<edgeBlocks, TPB, 0, s_side>>>(src, dst, e);
    cudaEventRecord(ev_join, s_side);

    // Main stream: weight cvt + LN1 (fp16) + projections (fp16 A+B).
    wcvt_kernel<<<(WTOTAL + TPB - 1) / TPB, TPB>>>(W_head, W_tail, W_ent, W_ff1, W_ff2);
    ln_kernel<<<rowBlocks, TPB>>>(feat, ln1_g, ln1_b, p_h16, n);
    dim3 gproj(1, (n + 127) / 128, 3);
    proj_gemm_kernel<<<gproj, 256>>>(p_h16, n);

    // Join: attn needs both CSR and projections.
    cudaStreamWaitEvent(0, ev_join, 0);

    // 4. attention logits + edge softmax (single pass)
    attn_kernel<<<rowBlocks, TPB>>>(attnw, n);

    // 5. diffusion: 5 hops (fp16 ping-pong), last hop fused with residual+LN2
    hop_kernel<<<rowBlocks, TPB>>>(p_fe16, p_g0, n);
    hop_kernel<<<rowBlocks, TPB>>>(p_g0, p_g1, n);
    hop_kernel<<<rowBlocks, TPB>>>(p_g1, p_g0, n);
    hop_kernel<<<rowBlocks, TPB>>>(p_g0, p_g1, n);
    hop_last_kernel<<<rowBlocks, TPB>>>(p_g1, feat, ln2_g, ln2_b, n);

    // 6. FFN (fp16 tensor cores, fp16 A+B, fp16 intermediate + fp16 rst add)
    dim3 gff1(DFF / 128, (n + 127) / 128);
    mma_gemm_kernel<true, true, false, true><<<gff1, 256>>>(
        p_x216, p_w16 + WOFF_FF1, b_ff1, nullptr, p_y116, n, DFF, D);
    dim3 gff2(D / 128, (n + 127) / 128);
    mma_gemm_kernel<false, true, true, false><<<gff2, 256>>>(
        p_y116, p_w16 + WOFF_FF2, b_ff2, p_rst16, d_out, n, D, DFF);
}